// round 13
// baseline (speedup 1.0000x reference)
#include <cuda_runtime.h>
#include <math.h>

#define BATCH 2
#define NV    4096
#define NP1   1024
#define NP2   256
#define FULLM 0xffffffffu

// ---------------------------------------------------------------------------
// Device scratch
// ---------------------------------------------------------------------------
__device__ float g_d0n  [3*896];
__device__ float g_dir1n[3*896];
__device__ float g_dir2n[3*1792];
__device__ float g_dir3n[3*1792];
__device__ float g_dir4n[3*3584];

__device__ int   g_idx10_0[BATCH*NV*10];
__device__ int   g_idx4_0 [BATCH*NV*4];
__device__ float g_dirs0  [BATCH*NV*10*3];
__device__ float g_fm0    [BATCH*NV*128];
__device__ float g_feat1  [BATCH*NV*1024];
__device__ float g_conv1  [BATCH*NV*128];
__device__ float g_fm1    [BATCH*NV*128];

__device__ float g_v1 [BATCH*NP1*3];
__device__ float g_f1 [BATCH*NP1*128];
__device__ int   g_idx10_1[BATCH*NP1*10];
__device__ int   g_idx4_1 [BATCH*NP1*4];
__device__ float g_dirs1  [BATCH*NP1*10*3];
__device__ float g_feat2  [BATCH*NP1*2048];
__device__ float g_conv2  [BATCH*NP1*256];
__device__ float g_fm2    [BATCH*NP1*256];
__device__ float g_feat3  [BATCH*NP1*2048];
__device__ float g_conv3  [BATCH*NP1*256];
__device__ float g_fm3    [BATCH*NP1*256];

__device__ float g_v2 [BATCH*NP2*3];
__device__ float g_f2 [BATCH*NP2*256];
__device__ int   g_idx10_2[BATCH*NP2*10];
__device__ float g_dirs2  [BATCH*NP2*10*3];
__device__ float g_feat4  [BATCH*NP2*4096];
__device__ float g_fm4    [BATCH*NP2*512];

__device__ int   g_n1[BATCH*NV];
__device__ int   g_n2[BATCH*NV];
__device__ float g_mean[512];
__device__ float g_rstd[512];
__device__ float g_bnp1[16*256];
__device__ float g_bnp2[16*256];
__device__ unsigned g_bn_ctr = 0;

// ---------------------------------------------------------------------------
// Math helpers
// ---------------------------------------------------------------------------
__device__ __forceinline__ float silu_unit(float y) {
    float u = y * y;
    float p = fmaf(u, 2.1357672e-5f, -2.1081349e-4f);
    p = fmaf(u, p, 2.0833333e-3f);
    p = fmaf(u, p, -2.0833333e-2f);
    p = fmaf(u, p, 0.25f);
    float s = fmaf(y, p, 0.5f);
    return y * s;
}

__device__ __forceinline__ float silu_full(float y) {
    return y / (1.0f + __expf(-y));
}

__device__ __forceinline__ float to_tf32(float x) {
    float r;
    asm("cvt.rna.tf32.f32 %0, %1;" : "=f"(r) : "f"(x));
    return r;
}

__device__ __forceinline__ void mma_tf32(float* c, const float* a, const float* b) {
    asm volatile(
        "mma.sync.aligned.m16n8k8.row.col.f32.tf32.tf32.f32 "
        "{%0,%1,%2,%3}, {%4,%5,%6,%7}, {%8,%9}, {%0,%1,%2,%3};"
        : "+f"(c[0]), "+f"(c[1]), "+f"(c[2]), "+f"(c[3])
        : "r"(__float_as_uint(a[0])), "r"(__float_as_uint(a[1])),
          "r"(__float_as_uint(a[2])), "r"(__float_as_uint(a[3])),
          "r"(__float_as_uint(b[0])), "r"(__float_as_uint(b[1])));
}

// ---------------------------------------------------------------------------
// knn device body (R10-proven): one warp per query, warp-shared sorted 11-list.
// smem: 4 float arrays of 256. blk indexes 8 queries.
// ---------------------------------------------------------------------------
__device__ void knn_dev(const float* __restrict__ v, int N,
                        int* __restrict__ idx10, int* __restrict__ idx4,
                        float* __restrict__ dirs, int blk, char* smem) {
    const int t = threadIdx.x;
    const int wid = t >> 5;
    const int lane = t & 31;
    const int q = blk * 8 + wid;
    const int b = q / N;
    const int i = q - b * N;
    const float* vb = v + (long)b * N * 3;
    const float px = vb[i * 3 + 0], py = vb[i * 3 + 1], pz = vb[i * 3 + 2];
    const float pq = px * px + py * py + pz * pz;

    float* sx = (float*)smem;
    float* sy = sx + 256;
    float* sz = sy + 256;
    float* sq = sz + 256;

    unsigned long long lst = 0xFFFFFFFFFFFFFFFFull;
    unsigned long long kmax_r = 0xFFFFFFFFFFFFFFFFull;

    for (int j0 = 0; j0 < N; j0 += 256) {
        __syncthreads();
        {
            int j = j0 + t;
            float cx = vb[j * 3 + 0];
            float cy = vb[j * 3 + 1];
            float cz = vb[j * 3 + 2];
            sx[t] = cx; sy[t] = cy; sz[t] = cz;
            sq[t] = cx * cx + cy * cy + cz * cz;
        }
        __syncthreads();
#pragma unroll
        for (int s = 0; s < 8; s++) {
            int jj = s * 32 + lane;
            float dot = px * sx[jj] + py * sy[jj] + pz * sz[jj];
            float dist = pq + sq[jj] - 2.0f * dot;
            unsigned bits = __float_as_uint(dist);
            unsigned u = bits ^ ((unsigned)((int)bits >> 31) | 0x80000000u);
            unsigned long long mykey =
                ((unsigned long long)u << 32) | (unsigned)(j0 + jj);
            unsigned ball = __ballot_sync(FULLM, mykey < kmax_r);
            while (ball) {
                int src = __ffs(ball) - 1;
                ball &= ball - 1;
                unsigned long long cand = __shfl_sync(FULLM, mykey, src);
                if (cand < kmax_r) {
                    unsigned below = __ballot_sync(FULLM, lst < cand);
                    int pos = __popc(below);
                    unsigned long long sh = __shfl_up_sync(FULLM, lst, 1);
                    if (lane < 11) {
                        if (lane == pos) lst = cand;
                        else if (lane > pos) lst = sh;
                    }
                    kmax_r = __shfl_sync(FULLM, lst, 10);
                }
            }
        }
    }

    int myidx = (int)(unsigned)(lst & 0xFFFFFFFFull);
    if (lane >= 1 && lane <= 10) {
        idx10[(long)q * 10 + (lane - 1)] = myidx;
        if (idx4 != 0 && lane <= 4)
            idx4[(long)q * 4 + (lane - 1)] = myidx;
        float dx = vb[myidx * 3 + 0] - px;
        float dy = vb[myidx * 3 + 1] - py;
        float dz = vb[myidx * 3 + 2] - pz;
        float nn = sqrtf(dx * dx + dy * dy + dz * dz);
        float r = 1.0f / fmaxf(nn, 1e-12f);
        dirs[(long)q * 30 + (lane - 1) * 3 + 0] = dx * r;
        dirs[(long)q * 30 + (lane - 1) * 3 + 1] = dy * r;
        dirs[(long)q * 30 + (lane - 1) * 3 + 2] = dz * r;
    }
}

// ---------------------------------------------------------------------------
// gemm device body (R10-proven): 128x128 tile, BK=16, warp 64x32, tf32 mma.
// smem layout: As = float[2][128][20] then Bs = float[2][16][136].
// ---------------------------------------------------------------------------
#define GEMM_SMEM_BYTES (2*128*20*4 + 2*16*136*4)

__device__ void gemm_dev(const float* __restrict__ A, const float* __restrict__ B,
                         const float* __restrict__ bias, float* __restrict__ C,
                         int M, int N, int K, int bx, int by, char* smem) {
    float (*As)[128][20] = (float (*)[128][20])smem;
    float (*Bs)[16][136] = (float (*)[16][136])(smem + 2*128*20*4);
    const int tid = threadIdx.x;
    const int warp = tid >> 5, lane = tid & 31;
    const int bm = by * 128;
    const int bn = bx * 128;
    const int wr = (warp & 1) * 64;
    const int wc = (warp >> 1) * 32;

    const int arow = tid >> 1;
    const int akb  = (tid & 1) * 8;
    const int brow = tid >> 4;
    const int bcb  = (tid & 15) * 8;

    const float* Ag = A + (long)(bm + arow) * K + akb;
    const float* Bg = B + (long)brow * N + bn + bcb;

    float acc[4][4][4];
#pragma unroll
    for (int mi = 0; mi < 4; mi++)
#pragma unroll
        for (int ni = 0; ni < 4; ni++)
#pragma unroll
            for (int r = 0; r < 4; r++) acc[mi][ni][r] = 0.0f;

    const int T = K >> 4;

    {
        float4 a0 = *(const float4*)(Ag);
        float4 a1 = *(const float4*)(Ag + 4);
        float4 b0 = *(const float4*)(Bg);
        float4 b1 = *(const float4*)(Bg + 4);
        As[0][arow][akb + 0] = to_tf32(a0.x); As[0][arow][akb + 1] = to_tf32(a0.y);
        As[0][arow][akb + 2] = to_tf32(a0.z); As[0][arow][akb + 3] = to_tf32(a0.w);
        As[0][arow][akb + 4] = to_tf32(a1.x); As[0][arow][akb + 5] = to_tf32(a1.y);
        As[0][arow][akb + 6] = to_tf32(a1.z); As[0][arow][akb + 7] = to_tf32(a1.w);
        Bs[0][brow][bcb + 0] = to_tf32(b0.x); Bs[0][brow][bcb + 1] = to_tf32(b0.y);
        Bs[0][brow][bcb + 2] = to_tf32(b0.z); Bs[0][brow][bcb + 3] = to_tf32(b0.w);
        Bs[0][brow][bcb + 4] = to_tf32(b1.x); Bs[0][brow][bcb + 5] = to_tf32(b1.y);
        Bs[0][brow][bcb + 6] = to_tf32(b1.z); Bs[0][brow][bcb + 7] = to_tf32(b1.w);
    }
    __syncthreads();

    const int lr = lane >> 2;
    const int lc = lane & 3;

    for (int t = 0; t < T; t++) {
        const int cur = t & 1;
        float4 a0, a1, b0, b1;
        if (t + 1 < T) {
            a0 = *(const float4*)(Ag + (t + 1) * 16);
            a1 = *(const float4*)(Ag + (t + 1) * 16 + 4);
            b0 = *(const float4*)(Bg + (long)(t + 1) * 16 * N);
            b1 = *(const float4*)(Bg + (long)(t + 1) * 16 * N + 4);
        }
#pragma unroll
        for (int kk = 0; kk < 16; kk += 8) {
            float af[4][4], bf[4][2];
#pragma unroll
            for (int mi = 0; mi < 4; mi++) {
                int r0 = wr + mi * 16 + lr;
                af[mi][0] = As[cur][r0][kk + lc];
                af[mi][1] = As[cur][r0 + 8][kk + lc];
                af[mi][2] = As[cur][r0][kk + lc + 4];
                af[mi][3] = As[cur][r0 + 8][kk + lc + 4];
            }
#pragma unroll
            for (int ni = 0; ni < 4; ni++) {
                int cb = wc + ni * 8 + lr;
                bf[ni][0] = Bs[cur][kk + lc][cb];
                bf[ni][1] = Bs[cur][kk + lc + 4][cb];
            }
#pragma unroll
            for (int mi = 0; mi < 4; mi++)
#pragma unroll
                for (int ni = 0; ni < 4; ni++)
                    mma_tf32(acc[mi][ni], af[mi], bf[ni]);
        }
        if (t + 1 < T) {
            const int nxt = cur ^ 1;
            As[nxt][arow][akb + 0] = to_tf32(a0.x); As[nxt][arow][akb + 1] = to_tf32(a0.y);
            As[nxt][arow][akb + 2] = to_tf32(a0.z); As[nxt][arow][akb + 3] = to_tf32(a0.w);
            As[nxt][arow][akb + 4] = to_tf32(a1.x); As[nxt][arow][akb + 5] = to_tf32(a1.y);
            As[nxt][arow][akb + 6] = to_tf32(a1.z); As[nxt][arow][akb + 7] = to_tf32(a1.w);
            Bs[nxt][brow][bcb + 0] = to_tf32(b0.x); Bs[nxt][brow][bcb + 1] = to_tf32(b0.y);
            Bs[nxt][brow][bcb + 2] = to_tf32(b0.z); Bs[nxt][brow][bcb + 3] = to_tf32(b0.w);
            Bs[nxt][brow][bcb + 4] = to_tf32(b1.x); Bs[nxt][brow][bcb + 5] = to_tf32(b1.y);
            Bs[nxt][brow][bcb + 6] = to_tf32(b1.z); Bs[nxt][brow][bcb + 7] = to_tf32(b1.w);
            __syncthreads();
        }
    }

#pragma unroll
    for (int mi = 0; mi < 4; mi++) {
        int row0 = bm + wr + mi * 16 + lr;
#pragma unroll
        for (int ni = 0; ni < 4; ni++) {
            int col = bn + wc + ni * 8 + lc * 2;
            float bx2 = bias[col], by2 = bias[col + 1];
            float2 o0, o1;
            o0.x = acc[mi][ni][0] + bx2; o0.y = acc[mi][ni][1] + by2;
            o1.x = acc[mi][ni][2] + bx2; o1.y = acc[mi][ni][3] + by2;
            *(float2*)(C + (long)row0 * N + col)       = o0;
            *(float2*)(C + (long)(row0 + 8) * N + col) = o1;
        }
    }
}

// ---------------------------------------------------------------------------
// nearest device body: 256 queries/block, smem-staged v1 & v2.
// smem layout: sx1[1024] sy1 sz1 sq1 sx2[256] sy2 sz2 sq2 (20480 B)
// ---------------------------------------------------------------------------
__device__ void nearest_dev(const float* __restrict__ x,
                            const float* __restrict__ v1,
                            const float* __restrict__ v2,
                            int* __restrict__ n1, int* __restrict__ n2,
                            int blk, char* smem) {
    float* sx1 = (float*)smem;
    float* sy1 = sx1 + NP1;
    float* sz1 = sy1 + NP1;
    float* sq1 = sz1 + NP1;
    float* sx2 = sq1 + NP1;
    float* sy2 = sx2 + NP2;
    float* sz2 = sy2 + NP2;
    float* sq2 = sz2 + NP2;
    int tid = threadIdx.x;
    int q = blk * 256 + tid;
    int b = q >> 12;
    const float* p1 = v1 + (long)b * NP1 * 3;
    const float* p2 = v2 + (long)b * NP2 * 3;
    for (int j = tid; j < NP1; j += 256) {
        float a = p1[j * 3], c = p1[j * 3 + 1], d = p1[j * 3 + 2];
        sx1[j] = a; sy1[j] = c; sz1[j] = d; sq1[j] = a * a + c * c + d * d;
    }
    for (int j = tid; j < NP2; j += 256) {
        float a = p2[j * 3], c = p2[j * 3 + 1], d = p2[j * 3 + 2];
        sx2[j] = a; sy2[j] = c; sz2[j] = d; sq2[j] = a * a + c * c + d * d;
    }
    __syncthreads();
    float px = x[q * 3], py = x[q * 3 + 1], pz = x[q * 3 + 2];
    float pq = px * px + py * py + pz * pz;
    float best = 1e30f; int bj = 0;
    for (int j = 0; j < NP1; j++) {
        float dist = pq + sq1[j] - 2.0f * (px * sx1[j] + py * sy1[j] + pz * sz1[j]);
        if (dist < best) { best = dist; bj = j; }
    }
    n1[q] = bj;
    best = 1e30f; bj = 0;
    for (int j = 0; j < NP2; j++) {
        float dist = pq + sq2[j] - 2.0f * (px * sx2[j] + py * sy2[j] + pz * sz2[j]);
        if (dist < best) { best = dist; bj = j; }
    }
    n2[q] = bj;
}

// ---------------------------------------------------------------------------
// mega0: knn level-0 (blocks 0..1023) + norm_all (blocks 1024..1058)
// ---------------------------------------------------------------------------
__global__ __launch_bounds__(256, 2)
void mega0_kernel(const float* __restrict__ x,
                  int* __restrict__ idx10_0, int* __restrict__ idx4_0,
                  float* __restrict__ dirs0,
                  const float* __restrict__ d0, const float* __restrict__ dir1,
                  const float* __restrict__ dir2, const float* __restrict__ dir3,
                  const float* __restrict__ dir4,
                  float* __restrict__ o0, float* __restrict__ o1,
                  float* __restrict__ o2, float* __restrict__ o3,
                  float* __restrict__ o4) {
    __shared__ __align__(16) char smem[4 * 256 * 4];
    int blk = blockIdx.x;
    if (blk < BATCH * NV / 8) {
        knn_dev(x, NV, idx10_0, idx4_0, dirs0, blk, smem);
    } else {
        int c = (blk - BATCH * NV / 8) * 256 + threadIdx.x;
        if (c >= 8960) return;
        const float* S; float* D; int W, col;
        if (c < 896)       { S = d0;   D = o0; W = 896;  col = c; }
        else if (c < 1792) { S = dir1; D = o1; W = 896;  col = c - 896; }
        else if (c < 3584) { S = dir2; D = o2; W = 1792; col = c - 1792; }
        else if (c < 5376) { S = dir3; D = o3; W = 1792; col = c - 3584; }
        else               { S = dir4; D = o4; W = 3584; col = c - 5376; }
        float xx = S[col], yy = S[W + col], zz = S[2 * W + col];
        float n = sqrtf(xx * xx + yy * yy + zz * zz);
        float r = 1.0f / fmaxf(n, 1e-12f);
        D[col] = xx * r; D[W + col] = yy * r; D[2 * W + col] = zz * r;
    }
}

// ---------------------------------------------------------------------------
// mega1: gemm2 (blocks 0..255) + knn level-1 (blocks 256..511)
// ---------------------------------------------------------------------------
__global__ __launch_bounds__(256, 2)
void mega1_kernel(const float* __restrict__ f1, const float* __restrict__ w2,
                  const float* __restrict__ b2, float* __restrict__ feat2,
                  const float* __restrict__ v1,
                  int* __restrict__ idx10_1, int* __restrict__ idx4_1,
                  float* __restrict__ dirs1) {
    __shared__ __align__(16) char smem[GEMM_SMEM_BYTES];
    int blk = blockIdx.x;
    if (blk < 256) {
        gemm_dev(f1, w2, b2, feat2, BATCH * NP1, 2048, 128, blk & 15, blk >> 4, smem);
    } else {
        knn_dev(v1, NP1, idx10_1, idx4_1, dirs1, blk - 256, smem);
    }
}

// ---------------------------------------------------------------------------
// mega2: gemm4 (blocks 0..127) + knn level-2 (128..191) + nearest (192..223)
// ---------------------------------------------------------------------------
__global__ __launch_bounds__(256, 2)
void mega2_kernel(const float* __restrict__ f2, const float* __restrict__ w4,
                  const float* __restrict__ b4, float* __restrict__ feat4,
                  const float* __restrict__ v2,
                  int* __restrict__ idx10_2, float* __restrict__ dirs2,
                  const float* __restrict__ x, const float* __restrict__ v1,
                  int* __restrict__ n1, int* __restrict__ n2) {
    __shared__ __align__(16) char smem[GEMM_SMEM_BYTES];
    int blk = blockIdx.x;
    if (blk < 128) {
        gemm_dev(f2, w4, b4, feat4, BATCH * NP2, 4096, 256, blk & 31, blk >> 5, smem);
    } else if (blk < 192) {
        knn_dev(v2, NP2, idx10_2, (int*)0, dirs2, blk - 128, smem);
    } else {
        nearest_dev(x, v1, v2, n1, n2, blk - 192, smem);
    }
}

// ---------------------------------------------------------------------------
// Standalone gemm (levels where nothing independent is available)
// ---------------------------------------------------------------------------
__global__ __launch_bounds__(256, 2)
void gemm_tf32_kernel(const float* __restrict__ A, const float* __restrict__ B,
                      const float* __restrict__ bias, float* __restrict__ C,
                      int M, int N, int K) {
    __shared__ __align__(16) char smem[GEMM_SMEM_BYTES];
    gemm_dev(A, B, bias, C, M, N, K, blockIdx.x, blockIdx.y, smem);
}

// ---------------------------------------------------------------------------
// conv_surface, float4, monotone-SiLU hoist
// ---------------------------------------------------------------------------
__global__ void conv_surface_kernel(const float* __restrict__ dirs,
                                    const float* __restrict__ dn,
                                    float* __restrict__ fm0) {
    int pt = blockIdx.x;
    int t = threadIdx.x;
    __shared__ float sd[30];
    if (t < 30) sd[t] = dirs[(long)pt * 30 + t];
    __syncwarp();
    float rx[10], ry[10], rz[10];
#pragma unroll
    for (int n = 0; n < 10; n++) { rx[n] = sd[3*n]; ry[n] = sd[3*n+1]; rz[n] = sd[3*n+2]; }
    int c4 = t * 4;
    float4 acc = make_float4(0.f, 0.f, 0.f, 0.f);
#pragma unroll
    for (int s = 0; s < 7; s++) {
        int col = s * 128 + c4;
        float4 dx = *(const float4*)(dn + col);
        float4 dy = *(const float4*)(dn + 896 + col);
        float4 dz = *(const float4*)(dn + 1792 + col);
        float4 m = make_float4(-1e30f, -1e30f, -1e30f, -1e30f);
#pragma unroll
        for (int n = 0; n < 10; n++) {
            m.x = fmaxf(m.x, rx[n]*dx.x + ry[n]*dy.x + rz[n]*dz.x);
            m.y = fmaxf(m.y, rx[n]*dx.y + ry[n]*dy.y + rz[n]*dz.y);
            m.z = fmaxf(m.z, rx[n]*dx.z + ry[n]*dy.z + rz[n]*dz.z);
            m.w = fmaxf(m.w, rx[n]*dx.w + ry[n]*dy.w + rz[n]*dz.w);
        }
        acc.x += silu_unit(m.x);
        acc.y += silu_unit(m.y);
        acc.z += silu_unit(m.z);
        acc.w += silu_unit(m.w);
    }
    float4 o;
    o.x = silu_full(acc.x); o.y = silu_full(acc.y);
    o.z = silu_full(acc.z); o.w = silu_full(acc.w);
    *(float4*)(fm0 + (long)pt * 128 + c4) = o;
}

// ---------------------------------------------------------------------------
// conv_layer, float4
// ---------------------------------------------------------------------------
template <int C>
__global__ void conv_layer_kernel(const float* __restrict__ feat,
                                  const float* __restrict__ dirs,
                                  const int* __restrict__ idx,
                                  const float* __restrict__ dirn,
                                  float* __restrict__ out, int Npts) {
    const int F = 8 * C;
    const int W = 7 * C;
    int pt = blockIdx.x;
    int b = pt / Npts;
    int t = threadIdx.x;
    __shared__ float sd[30];
    __shared__ int soff[10];
    if (t < 10) {
        int j = idx[(long)pt * 10 + t];
        soff[t] = (b * Npts + j) * F + C;
    }
    if (t < 30) sd[t] = dirs[(long)pt * 30 + t];
    __syncthreads();
    float rx[10], ry[10], rz[10];
    int off[10];
#pragma unroll
    for (int n = 0; n < 10; n++) {
        rx[n] = sd[3*n]; ry[n] = sd[3*n+1]; rz[n] = sd[3*n+2];
        off[n] = soff[n];
    }
    int c4 = t * 4;
    float4 center = *(const float4*)(feat + (long)pt * F + c4);
    float4 acc = make_float4(0.f, 0.f, 0.f, 0.f);
#pragma unroll
    for (int s = 0; s < 7; s++) {
        int col = s * C + c4;
        float4 dx = *(const float4*)(dirn + col);
        float4 dy = *(const float4*)(dirn + W + col);
        float4 dz = *(const float4*)(dirn + 2 * W + col);
        float4 m = make_float4(-1e30f, -1e30f, -1e30f, -1e30f);
#pragma unroll
        for (int n = 0; n < 10; n++) {
            float4 f = *(const float4*)(feat + off[n] + col);
            m.x = fmaxf(m.x, silu_unit(rx[n]*dx.x + ry[n]*dy.x + rz[n]*dz.x) * f.x);
            m.y = fmaxf(m.y, silu_unit(rx[n]*dx.y + ry[n]*dy.y + rz[n]*dz.y) * f.y);
            m.z = fmaxf(m.z, silu_unit(rx[n]*dx.z + ry[n]*dy.z + rz[n]*dz.z) * f.z);
            m.w = fmaxf(m.w, silu_unit(rx[n]*dx.w + ry[n]*dy.w + rz[n]*dz.w) * f.w);
        }
        acc.x += m.x; acc.y += m.y; acc.z += m.z; acc.w += m.w;
    }
    float4 o;
    o.x = center.x + acc.x; o.y = center.y + acc.y;
    o.z = center.z + acc.z; o.w = center.w + acc.w;
    *(float4*)(out + (long)pt * C + c4) = o;
}

// ---------------------------------------------------------------------------
// BatchNorm stats, single launch: partial sums + last-block finish
// ---------------------------------------------------------------------------
__global__ void bn_stats_kernel(const float* __restrict__ X, int R, int C,
                                float* __restrict__ ps, float* __restrict__ ps2,
                                float* __restrict__ mean, float* __restrict__ rstd) {
    int lane = threadIdx.x & 31;
    int w = threadIdx.x >> 5;
    int c = blockIdx.x * 32 + lane;
    int chunk = blockIdx.y;
    int rowsPer = R >> 4;
    int r0 = chunk * rowsPer;
    float s = 0.0f, s2 = 0.0f;
    for (int r = r0 + w; r < r0 + rowsPer; r += 8) {
        float v = X[(long)r * C + c];
        s += v; s2 += v * v;
    }
    __shared__ float sh[8][32], sh2[8][32];
    sh[w][lane] = s; sh2[w][lane] = s2;
    __syncthreads();
    if (w == 0) {
#pragma unroll
        for (int i = 1; i < 8; i++) { s += sh[i][lane]; s2 += sh2[i][lane]; }
        ps [chunk * C + c] = s;
        ps2[chunk * C + c] = s2;
    }
    __shared__ bool isLast;
    __threadfence();
    __syncthreads();
    if (threadIdx.x == 0) {
        unsigned total = gridDim.x * gridDim.y;
        unsigned old = atomicAdd(&g_bn_ctr, 1u);
        isLast = (old == total - 1);
    }
    __syncthreads();
    if (isLast) {
        int cc = threadIdx.x;
        if (cc < C) {
            float ts = 0.0f, ts2 = 0.0f;
#pragma unroll
            for (int k = 0; k < 16; k++) { ts += ps[k * C + cc]; ts2 += ps2[k * C + cc]; }
            float m = ts / (float)R;
            float var = ts2 / (float)R - m * m;
            mean[cc] = m;
            rstd[cc] = rsqrtf(var + 1e-5f);
        }
        __syncthreads();
        if (threadIdx.x == 0) g_bn_ctr = 0;
    }
}

__global__ void bn_apply_silu_kernel(const float* __restrict__ X,
                                     const float* __restrict__ mean, const float* __restrict__ rstd,
                                     const float* __restrict__ g, const float* __restrict__ bb,
                                     float* __restrict__ Y, int total, int C) {
    int i = blockIdx.x * 256 + threadIdx.x;
    if (i >= total) return;
    int c = i & (C - 1);
    float y = (X[i] - mean[c]) * rstd[c] * g[c] + bb[c];
    Y[i] = silu_full(y);
}

// ---------------------------------------------------------------------------
// Fused 4-NN max-pool + permutation gather (float4)
// ---------------------------------------------------------------------------
template <int C>
__global__ void pool_gather_kernel(const float* __restrict__ fm, const int* __restrict__ idx4,
                                   const int* __restrict__ perm, const float* __restrict__ vin,
                                   float* __restrict__ fout, float* __restrict__ vout,
                                   int Nin, int Pout) {
    int bp = blockIdx.x;
    int b = bp / Pout;
    int p = bp - b * Pout;
    int t = threadIdx.x;
    __shared__ int si;
    __shared__ int sj[4];
    if (t == 0) si = perm[p];
    __syncthreads();
    if (t < 4) sj[t] = idx4[((long)b * Nin + si) * 4 + t];
    __syncthreads();
    float4 m = make_float4(-1e30f, -1e30f, -1e30f, -1e30f);
#pragma unroll
    for (int n = 0; n < 4; n++) {
        float4 f = *(const float4*)(fm + ((long)b * Nin + sj[n]) * C + t * 4);
        m.x = fmaxf(m.x, f.x); m.y = fmaxf(m.y, f.y);
        m.z = fmaxf(m.z, f.z); m.w = fmaxf(m.w, f.w);
    }
    *(float4*)(fout + (long)bp * C + t * 4) = m;
    if (t == 0) {
        vout[(long)bp * 3 + 0] = vin[((long)b * Nin + si) * 3 + 0];
        vout[(long)bp * 3 + 1] = vin[((long)b * Nin + si) * 3 + 1];
        vout[(long)bp * 3 + 2] = vin[((long)b * Nin + si) * 3 + 2];
    }
}

// ---------------------------------------------------------------------------
// Final concat + upsample (float4)
// ---------------------------------------------------------------------------
__global__ void assemble_kernel(const float* __restrict__ fm0, const float* __restrict__ fm1,
                                const float* __restrict__ fm2, const float* __restrict__ fm3,
                                const float* __restrict__ fm4,
                                const int* __restrict__ n1, const int* __restrict__ n2,
                                float* __restrict__ out) {
    int pt = blockIdx.x;
    int b = pt >> 12;
    int j1 = n1[pt];
    int j2 = n2[pt];
    const float4* s0 = (const float4*)(fm0 + (long)pt * 128);
    const float4* s1 = (const float4*)(fm1 + (long)pt * 128);
    const float4* s2 = (const float4*)(fm2 + ((long)b * NP1 + j1) * 256);
    const float4* s3 = (const float4*)(fm3 + ((long)b * NP1 + j1) * 256);
    const float4* s4 = (const float4*)(fm4 + ((long)b * NP2 + j2) * 512);
    float4* o = (float4*)(out + (long)pt * 1280);
    for (int c = threadIdx.x; c < 320; c += 256) {
        float4 v;
        if (c < 32)       v = s0[c];
        else if (c < 64)  v = s1[c - 32];
        else if (c < 128) v = s2[c - 64];
        else if (c < 192) v = s3[c - 128];
        else              v = s4[c - 192];
        o[c] = v;
    }
}

// ---------------------------------------------------------------------------
// Host driver
// ---------------------------------------------------------------------------
extern "C" void kernel_launch(void* const* d_in, const int* in_sizes, int n_in,
                              void* d_out, int out_size) {
    const float* x    = (const float*)d_in[0];
    const float* d0   = (const float*)d_in[1];
    const float* w1   = (const float*)d_in[2];
    const float* b1   = (const float*)d_in[3];
    const float* dir1 = (const float*)d_in[4];
    const float* g1   = (const float*)d_in[5];
    const float* bb1  = (const float*)d_in[6];
    const float* w2   = (const float*)d_in[7];
    const float* b2   = (const float*)d_in[8];
    const float* dir2 = (const float*)d_in[9];
    const float* g2   = (const float*)d_in[10];
    const float* bb2  = (const float*)d_in[11];
    const float* w3   = (const float*)d_in[12];
    const float* b3   = (const float*)d_in[13];
    const float* dir3 = (const float*)d_in[14];
    const float* g3   = (const float*)d_in[15];
    const float* bb3  = (const float*)d_in[16];
    const float* w4   = (const float*)d_in[17];
    const float* b4   = (const float*)d_in[18];
    const float* dir4 = (const float*)d_in[19];
    const int* perm1  = (const int*)d_in[20];
    const int* perm2  = (const int*)d_in[21];
    float* out = (float*)d_out;

    float *d0n, *dir1n, *dir2n, *dir3n, *dir4n;
    int *idx10_0, *idx4_0, *idx10_1, *idx4_1, *idx10_2, *n1, *n2;
    float *dirs0, *dirs1, *dirs2;
    float *fm0, *feat1, *conv1, *fm1, *v1, *f1;
    float *feat2, *conv2, *fm2, *feat3, *conv3, *fm3;
    float *v2, *f2, *feat4, *fm4, *mean, *rstd, *bnp1, *bnp2;

    cudaGetSymbolAddress((void**)&d0n,  g_d0n);
    cudaGetSymbolAddress((void**)&dir1n, g_dir1n);
    cudaGetSymbolAddress((void**)&dir2n, g_dir2n);
    cudaGetSymbolAddress((void**)&dir3n, g_dir3n);
    cudaGetSymbolAddress((void**)&dir4n, g_dir4n);
    cudaGetSymbolAddress((void**)&idx10_0, g_idx10_0);
    cudaGetSymbolAddress((void**)&idx4_0,  g_idx4_0);
    cudaGetSymbolAddress((void**)&dirs0,   g_dirs0);
    cudaGetSymbolAddress((void**)&fm0,     g_fm0);
    cudaGetSymbolAddress((void**)&feat1,   g_feat1);
    cudaGetSymbolAddress((void**)&conv1,   g_conv1);
    cudaGetSymbolAddress((void**)&fm1,     g_fm1);
    cudaGetSymbolAddress((void**)&v1,      g_v1);
    cudaGetSymbolAddress((void**)&f1,      g_f1);
    cudaGetSymbolAddress((void**)&idx10_1, g_idx10_1);
    cudaGetSymbolAddress((void**)&idx4_1,  g_idx4_1);
    cudaGetSymbolAddress((void**)&dirs1,   g_dirs1);
    cudaGetSymbolAddress((void**)&feat2,   g_feat2);
    cudaGetSymbolAddress((void**)&conv2,   g_conv2);
    cudaGetSymbolAddress((void**)&fm2,     g_fm2);
    cudaGetSymbolAddress((void**)&feat3,   g_feat3);
    cudaGetSymbolAddress((void**)&conv3,   g_conv3);
    cudaGetSymbolAddress((void**)&fm3,     g_fm3);
    cudaGetSymbolAddress((void**)&v2,      g_v2);
    cudaGetSymbolAddress((void**)&f2,      g_f2);
    cudaGetSymbolAddress((void**)&idx10_2, g_idx10_2);
    cudaGetSymbolAddress((void**)&dirs2,   g_dirs2);
    cudaGetSymbolAddress((void**)&feat4,   g_feat4);
    cudaGetSymbolAddress((void**)&fm4,     g_fm4);
    cudaGetSymbolAddress((void**)&n1,      g_n1);
    cudaGetSymbolAddress((void**)&n2,      g_n2);
    cudaGetSymbolAddress((void**)&mean,    g_mean);
    cudaGetSymbolAddress((void**)&rstd,    g_rstd);
    cudaGetSymbolAddress((void**)&bnp1,    g_bnp1);
    cudaGetSymbolAddress((void**)&bnp2,    g_bnp2);

    // ---- Level 0 (V = 4096) ----  (index 3 = conv_layer<128> -> profiled)
    mega0_kernel<<<BATCH * NV / 8 + 35, 256>>>(x, idx10_0, idx4_0, dirs0,
                                               d0, dir1, dir2, dir3, dir4,
                                               d0n, dir1n, dir2n, dir3n, dir4n); // 0
    conv_surface_kernel<<<BATCH * NV, 32>>>(dirs0, d0n, fm0);                    // 1
    gemm_tf32_kernel<<<dim3(1024 / 128, (BATCH * NV) / 128), 256>>>(fm0, w1, b1, feat1, BATCH * NV, 1024, 128); // 2
    conv_layer_kernel<128><<<BATCH * NV, 32>>>(feat1, dirs0, idx10_0, dir1n, conv1, NV); // 3 <-- profiled
    bn_stats_kernel<<<dim3(128 / 32, 16), 256>>>(conv1, BATCH * NV, 128, bnp1, bnp2, mean, rstd);
    bn_apply_silu_kernel<<<(BATCH * NV * 128 + 255) / 256, 256>>>(conv1, mean, rstd, g1, bb1, fm1, BATCH * NV * 128, 128);
    pool_gather_kernel<128><<<BATCH * NP1, 32>>>(fm1, idx4_0, perm1, x, f1, v1, NV, NP1);

    // ---- Level 1 (V = 1024) ----
    mega1_kernel<<<512, 256>>>(f1, w2, b2, feat2, v1, idx10_1, idx4_1, dirs1);
    conv_layer_kernel<256><<<BATCH * NP1, 64>>>(feat2, dirs1, idx10_1, dir2n, conv2, NP1);
    bn_stats_kernel<<<dim3(256 / 32, 16), 256>>>(conv2, BATCH * NP1, 256, bnp1, bnp2, mean, rstd);
    bn_apply_silu_kernel<<<(BATCH * NP1 * 256 + 255) / 256, 256>>>(conv2, mean, rstd, g2, bb2, fm2, BATCH * NP1 * 256, 256);
    gemm_tf32_kernel<<<dim3(2048 / 128, (BATCH * NP1) / 128), 256>>>(fm2, w3, b3, feat3, BATCH * NP1, 2048, 256);
    conv_layer_kernel<256><<<BATCH * NP1, 64>>>(feat3, dirs1, idx10_1, dir3n, conv3, NP1);
    bn_stats_kernel<<<dim3(256 / 32, 16), 256>>>(conv3, BATCH * NP1, 256, bnp1, bnp2, mean, rstd);
    bn_apply_silu_kernel<<<(BATCH * NP1 * 256 + 255) / 256, 256>>>(conv3, mean, rstd, g3, bb3, fm3, BATCH * NP1 * 256, 256);
    pool_gather_kernel<256><<<BATCH * NP2, 64>>>(fm3, idx4_1, perm2, v1, f2, v2, NP1, NP2);

    // ---- Level 2 (V = 256) + nearest ----
    mega2_kernel<<<224, 256>>>(f2, w4, b4, feat4, v2, idx10_2, dirs2, x, v1, n1, n2);
    conv_layer_kernel<512><<<BATCH * NP2, 128>>>(feat4, dirs2, idx10_2, dir4n, fm4, NP2);

    // ---- Concat ----
    assemble_kernel<<<BATCH * NV, 256>>>(fm0, fm1, fm2, fm3, fm4, n1, n2, out);
}

// round 14
// speedup vs baseline: 1.3997x; 1.3997x over previous
#include <cuda_runtime.h>
#include <math.h>

#define BATCH 2
#define NV    4096
#define NP1   1024
#define NP2   256
#define FULLM 0xffffffffu

// ---------------------------------------------------------------------------
// Device scratch
// ---------------------------------------------------------------------------
__device__ float g_d0n  [3*896];
__device__ float g_dir1n[3*896];
__device__ float g_dir2n[3*1792];
__device__ float g_dir3n[3*1792];
__device__ float g_dir4n[3*3584];

__device__ int   g_idx10_0[BATCH*NV*10];
__device__ int   g_idx4_0 [BATCH*NV*4];
__device__ float g_dirs0  [BATCH*NV*10*3];
__device__ float g_fm0    [BATCH*NV*128];
__device__ float g_feat1  [BATCH*NV*1024];
__device__ float g_conv1  [BATCH*NV*128];
__device__ float g_fm1    [BATCH*NV*128];

__device__ float g_v1 [BATCH*NP1*3];
__device__ float g_f1 [BATCH*NP1*128];
__device__ int   g_idx10_1[BATCH*NP1*10];
__device__ int   g_idx4_1 [BATCH*NP1*4];
__device__ float g_dirs1  [BATCH*NP1*10*3];
__device__ float g_feat2  [BATCH*NP1*2048];
__device__ float g_conv2  [BATCH*NP1*256];
__device__ float g_fm2    [BATCH*NP1*256];
__device__ float g_feat3  [BATCH*NP1*2048];
__device__ float g_conv3  [BATCH*NP1*256];
__device__ float g_fm3    [BATCH*NP1*256];

__device__ float g_v2 [BATCH*NP2*3];
__device__ float g_f2 [BATCH*NP2*256];
__device__ int   g_idx10_2[BATCH*NP2*10];
__device__ float g_dirs2  [BATCH*NP2*10*3];
__device__ float g_feat4  [BATCH*NP2*4096];
__device__ float g_fm4    [BATCH*NP2*512];

__device__ int   g_n1[BATCH*NV];
__device__ int   g_n2[BATCH*NV];
__device__ float g_mean[512];
__device__ float g_rstd[512];
__device__ float g_bnp1[16*256];
__device__ float g_bnp2[16*256];
__device__ unsigned g_bn_ctr = 0;

// ---------------------------------------------------------------------------
// Math helpers
// ---------------------------------------------------------------------------
__device__ __forceinline__ float silu_unit(float y) {
    float u = y * y;
    float p = fmaf(u, 2.1357672e-5f, -2.1081349e-4f);
    p = fmaf(u, p, 2.0833333e-3f);
    p = fmaf(u, p, -2.0833333e-2f);
    p = fmaf(u, p, 0.25f);
    float s = fmaf(y, p, 0.5f);
    return y * s;
}

__device__ __forceinline__ float silu_full(float y) {
    return y / (1.0f + __expf(-y));
}

__device__ __forceinline__ float to_tf32(float x) {
    float r;
    asm("cvt.rna.tf32.f32 %0, %1;" : "=f"(r) : "f"(x));
    return r;
}

__device__ __forceinline__ void mma_tf32(float* c, const float* a, const float* b) {
    asm volatile(
        "mma.sync.aligned.m16n8k8.row.col.f32.tf32.tf32.f32 "
        "{%0,%1,%2,%3}, {%4,%5,%6,%7}, {%8,%9}, {%0,%1,%2,%3};"
        : "+f"(c[0]), "+f"(c[1]), "+f"(c[2]), "+f"(c[3])
        : "r"(__float_as_uint(a[0])), "r"(__float_as_uint(a[1])),
          "r"(__float_as_uint(a[2])), "r"(__float_as_uint(a[3])),
          "r"(__float_as_uint(b[0])), "r"(__float_as_uint(b[1])));
}

// ---------------------------------------------------------------------------
// Fused column-normalize of all 5 direction matrices
// ---------------------------------------------------------------------------
__global__ void norm_all_kernel(const float* __restrict__ d0, const float* __restrict__ dir1,
                                const float* __restrict__ dir2, const float* __restrict__ dir3,
                                const float* __restrict__ dir4,
                                float* __restrict__ o0, float* __restrict__ o1,
                                float* __restrict__ o2, float* __restrict__ o3,
                                float* __restrict__ o4) {
    int c = blockIdx.x * 256 + threadIdx.x;
    if (c >= 8960) return;
    const float* S; float* D; int W, col;
    if (c < 896)       { S = d0;   D = o0; W = 896;  col = c; }
    else if (c < 1792) { S = dir1; D = o1; W = 896;  col = c - 896; }
    else if (c < 3584) { S = dir2; D = o2; W = 1792; col = c - 1792; }
    else if (c < 5376) { S = dir3; D = o3; W = 1792; col = c - 3584; }
    else               { S = dir4; D = o4; W = 3584; col = c - 5376; }
    float x = S[col], y = S[W + col], z = S[2 * W + col];
    float n = sqrtf(x * x + y * y + z * z);
    float r = 1.0f / fmaxf(n, 1e-12f);
    D[col] = x * r; D[W + col] = y * r; D[2 * W + col] = z * r;
}

// ---------------------------------------------------------------------------
// Warp-cooperative exact kNN (k=10 + self), fused unit-direction output.
// ---------------------------------------------------------------------------
__global__ void knn_warp_kernel(const float* __restrict__ v, int N,
                                int* __restrict__ idx10, int* __restrict__ idx4,
                                float* __restrict__ dirs) {
    const int t = threadIdx.x;
    const int wid = t >> 5;
    const int lane = t & 31;
    const int q = blockIdx.x * 8 + wid;
    const int b = q / N;
    const int i = q - b * N;
    const float* vb = v + (long)b * N * 3;
    const float px = vb[i * 3 + 0], py = vb[i * 3 + 1], pz = vb[i * 3 + 2];
    const float pq = px * px + py * py + pz * pz;

    unsigned long long lst = 0xFFFFFFFFFFFFFFFFull;
    unsigned long long kmax_r = 0xFFFFFFFFFFFFFFFFull;

    __shared__ float sx[256], sy[256], sz[256], sq[256];

    for (int j0 = 0; j0 < N; j0 += 256) {
        __syncthreads();
        {
            int j = j0 + t;
            float cx = vb[j * 3 + 0];
            float cy = vb[j * 3 + 1];
            float cz = vb[j * 3 + 2];
            sx[t] = cx; sy[t] = cy; sz[t] = cz;
            sq[t] = cx * cx + cy * cy + cz * cz;
        }
        __syncthreads();
#pragma unroll
        for (int s = 0; s < 8; s++) {
            int jj = s * 32 + lane;
            float dot = px * sx[jj] + py * sy[jj] + pz * sz[jj];
            float dist = pq + sq[jj] - 2.0f * dot;
            unsigned bits = __float_as_uint(dist);
            unsigned u = bits ^ ((unsigned)((int)bits >> 31) | 0x80000000u);
            unsigned long long mykey =
                ((unsigned long long)u << 32) | (unsigned)(j0 + jj);
            unsigned ball = __ballot_sync(FULLM, mykey < kmax_r);
            while (ball) {
                int src = __ffs(ball) - 1;
                ball &= ball - 1;
                unsigned long long cand = __shfl_sync(FULLM, mykey, src);
                if (cand < kmax_r) {
                    unsigned below = __ballot_sync(FULLM, lst < cand);
                    int pos = __popc(below);
                    unsigned long long sh = __shfl_up_sync(FULLM, lst, 1);
                    if (lane < 11) {
                        if (lane == pos) lst = cand;
                        else if (lane > pos) lst = sh;
                    }
                    kmax_r = __shfl_sync(FULLM, lst, 10);
                }
            }
        }
    }

    int myidx = (int)(unsigned)(lst & 0xFFFFFFFFull);
    if (lane >= 1 && lane <= 10) {
        idx10[(long)q * 10 + (lane - 1)] = myidx;
        if (idx4 != 0 && lane <= 4)
            idx4[(long)q * 4 + (lane - 1)] = myidx;
        float dx = vb[myidx * 3 + 0] - px;
        float dy = vb[myidx * 3 + 1] - py;
        float dz = vb[myidx * 3 + 2] - pz;
        float nn = sqrtf(dx * dx + dy * dy + dz * dz);
        float r = 1.0f / fmaxf(nn, 1e-12f);
        dirs[(long)q * 30 + (lane - 1) * 3 + 0] = dx * r;
        dirs[(long)q * 30 + (lane - 1) * 3 + 1] = dy * r;
        dirs[(long)q * 30 + (lane - 1) * 3 + 2] = dz * r;
    }
}

// ---------------------------------------------------------------------------
// conv_surface, float4, monotone-SiLU hoist, 4 points per 128-thr block
// ---------------------------------------------------------------------------
__global__ void conv_surface_kernel(const float* __restrict__ dirs,
                                    const float* __restrict__ dn,
                                    float* __restrict__ fm0) {
    int lp = threadIdx.x >> 5;          // local point 0..3
    int t = threadIdx.x & 31;
    int pt = blockIdx.x * 4 + lp;
    __shared__ float sd[4][30];
    if (t < 30) sd[lp][t] = dirs[(long)pt * 30 + t];
    __syncwarp();
    float rx[10], ry[10], rz[10];
#pragma unroll
    for (int n = 0; n < 10; n++) { rx[n] = sd[lp][3*n]; ry[n] = sd[lp][3*n+1]; rz[n] = sd[lp][3*n+2]; }
    int c4 = t * 4;
    float4 acc = make_float4(0.f, 0.f, 0.f, 0.f);
#pragma unroll
    for (int s = 0; s < 7; s++) {
        int col = s * 128 + c4;
        float4 dx = *(const float4*)(dn + col);
        float4 dy = *(const float4*)(dn + 896 + col);
        float4 dz = *(const float4*)(dn + 1792 + col);
        float4 m = make_float4(-1e30f, -1e30f, -1e30f, -1e30f);
#pragma unroll
        for (int n = 0; n < 10; n++) {
            m.x = fmaxf(m.x, rx[n]*dx.x + ry[n]*dy.x + rz[n]*dz.x);
            m.y = fmaxf(m.y, rx[n]*dx.y + ry[n]*dy.y + rz[n]*dz.y);
            m.z = fmaxf(m.z, rx[n]*dx.z + ry[n]*dy.z + rz[n]*dz.z);
            m.w = fmaxf(m.w, rx[n]*dx.w + ry[n]*dy.w + rz[n]*dz.w);
        }
        acc.x += silu_unit(m.x);
        acc.y += silu_unit(m.y);
        acc.z += silu_unit(m.z);
        acc.w += silu_unit(m.w);
    }
    float4 o;
    o.x = silu_full(acc.x); o.y = silu_full(acc.y);
    o.z = silu_full(acc.z); o.w = silu_full(acc.w);
    *(float4*)(fm0 + (long)pt * 128 + c4) = o;
}

// ---------------------------------------------------------------------------
// TF32 tensor-core GEMM with bias (R10 config: 128x128 tile, warp 64x32)
// ---------------------------------------------------------------------------
__global__ __launch_bounds__(256, 2)
void gemm_tf32_kernel(const float* __restrict__ A, const float* __restrict__ B,
                      const float* __restrict__ bias, float* __restrict__ C,
                      int M, int N, int K) {
    __shared__ float As[2][128][20];
    __shared__ float Bs[2][16][136];
    const int tid = threadIdx.x;
    const int warp = tid >> 5, lane = tid & 31;
    const int bm = blockIdx.y * 128;
    const int bn = blockIdx.x * 128;
    const int wr = (warp & 1) * 64;
    const int wc = (warp >> 1) * 32;

    const int arow = tid >> 1;
    const int akb  = (tid & 1) * 8;
    const int brow = tid >> 4;
    const int bcb  = (tid & 15) * 8;

    const float* Ag = A + (long)(bm + arow) * K + akb;
    const float* Bg = B + (long)brow * N + bn + bcb;

    float acc[4][4][4];
#pragma unroll
    for (int mi = 0; mi < 4; mi++)
#pragma unroll
        for (int ni = 0; ni < 4; ni++)
#pragma unroll
            for (int r = 0; r < 4; r++) acc[mi][ni][r] = 0.0f;

    const int T = K >> 4;

    {
        float4 a0 = *(const float4*)(Ag);
        float4 a1 = *(const float4*)(Ag + 4);
        float4 b0 = *(const float4*)(Bg);
        float4 b1 = *(const float4*)(Bg + 4);
        As[0][arow][akb + 0] = to_tf32(a0.x); As[0][arow][akb + 1] = to_tf32(a0.y);
        As[0][arow][akb + 2] = to_tf32(a0.z); As[0][arow][akb + 3] = to_tf32(a0.w);
        As[0][arow][akb + 4] = to_tf32(a1.x); As[0][arow][akb + 5] = to_tf32(a1.y);
        As[0][arow][akb + 6] = to_tf32(a1.z); As[0][arow][akb + 7] = to_tf32(a1.w);
        Bs[0][brow][bcb + 0] = to_tf32(b0.x); Bs[0][brow][bcb + 1] = to_tf32(b0.y);
        Bs[0][brow][bcb + 2] = to_tf32(b0.z); Bs[0][brow][bcb + 3] = to_tf32(b0.w);
        Bs[0][brow][bcb + 4] = to_tf32(b1.x); Bs[0][brow][bcb + 5] = to_tf32(b1.y);
        Bs[0][brow][bcb + 6] = to_tf32(b1.z); Bs[0][brow][bcb + 7] = to_tf32(b1.w);
    }
    __syncthreads();

    const int lr = lane >> 2;
    const int lc = lane & 3;

    for (int t = 0; t < T; t++) {
        const int cur = t & 1;
        float4 a0, a1, b0, b1;
        if (t + 1 < T) {
            a0 = *(const float4*)(Ag + (t + 1) * 16);
            a1 = *(const float4*)(Ag + (t + 1) * 16 + 4);
            b0 = *(const float4*)(Bg + (long)(t + 1) * 16 * N);
            b1 = *(const float4*)(Bg + (long)(t + 1) * 16 * N + 4);
        }
#pragma unroll
        for (int kk = 0; kk < 16; kk += 8) {
            float af[4][4], bf[4][2];
#pragma unroll
            for (int mi = 0; mi < 4; mi++) {
                int r0 = wr + mi * 16 + lr;
                af[mi][0] = As[cur][r0][kk + lc];
                af[mi][1] = As[cur][r0 + 8][kk + lc];
                af[mi][2] = As[cur][r0][kk + lc + 4];
                af[mi][3] = As[cur][r0 + 8][kk + lc + 4];
            }
#pragma unroll
            for (int ni = 0; ni < 4; ni++) {
                int cb = wc + ni * 8 + lr;
                bf[ni][0] = Bs[cur][kk + lc][cb];
                bf[ni][1] = Bs[cur][kk + lc + 4][cb];
            }
#pragma unroll
            for (int mi = 0; mi < 4; mi++)
#pragma unroll
                for (int ni = 0; ni < 4; ni++)
                    mma_tf32(acc[mi][ni], af[mi], bf[ni]);
        }
        if (t + 1 < T) {
            const int nxt = cur ^ 1;
            As[nxt][arow][akb + 0] = to_tf32(a0.x); As[nxt][arow][akb + 1] = to_tf32(a0.y);
            As[nxt][arow][akb + 2] = to_tf32(a0.z); As[nxt][arow][akb + 3] = to_tf32(a0.w);
            As[nxt][arow][akb + 4] = to_tf32(a1.x); As[nxt][arow][akb + 5] = to_tf32(a1.y);
            As[nxt][arow][akb + 6] = to_tf32(a1.z); As[nxt][arow][akb + 7] = to_tf32(a1.w);
            Bs[nxt][brow][bcb + 0] = to_tf32(b0.x); Bs[nxt][brow][bcb + 1] = to_tf32(b0.y);
            Bs[nxt][brow][bcb + 2] = to_tf32(b0.z); Bs[nxt][brow][bcb + 3] = to_tf32(b0.w);
            Bs[nxt][brow][bcb + 4] = to_tf32(b1.x); Bs[nxt][brow][bcb + 5] = to_tf32(b1.y);
            Bs[nxt][brow][bcb + 6] = to_tf32(b1.z); Bs[nxt][brow][bcb + 7] = to_tf32(b1.w);
            __syncthreads();
        }
    }

#pragma unroll
    for (int mi = 0; mi < 4; mi++) {
        int row0 = bm + wr + mi * 16 + lr;
#pragma unroll
        for (int ni = 0; ni < 4; ni++) {
            int col = bn + wc + ni * 8 + lc * 2;
            float bx = bias[col], by = bias[col + 1];
            float2 o0, o1;
            o0.x = acc[mi][ni][0] + bx; o0.y = acc[mi][ni][1] + by;
            o1.x = acc[mi][ni][2] + bx; o1.y = acc[mi][ni][3] + by;
            *(float2*)(C + (long)row0 * N + col)       = o0;
            *(float2*)(C + (long)(row0 + 8) * N + col) = o1;
        }
    }
}

// ---------------------------------------------------------------------------
// conv_layer, float4, P points per block (C/4 threads per point)
// ---------------------------------------------------------------------------
template <int C, int P>
__global__ void conv_layer_kernel(const float* __restrict__ feat,
                                  const float* __restrict__ dirs,
                                  const int* __restrict__ idx,
                                  const float* __restrict__ dirn,
                                  float* __restrict__ out, int Npts) {
    const int F = 8 * C;
    const int W = 7 * C;
    const int TPP = C / 4;
    int lp = threadIdx.x / TPP;
    int t = threadIdx.x - lp * TPP;
    int pt = blockIdx.x * P + lp;
    int b = pt / Npts;
    __shared__ float sd[P][30];
    __shared__ int soff[P][10];
    if (t < 10) {
        int j = idx[(long)pt * 10 + t];
        soff[lp][t] = (b * Npts + j) * F + C;
    }
    if (t < 30) sd[lp][t] = dirs[(long)pt * 30 + t];
    __syncthreads();
    float rx[10], ry[10], rz[10];
    int off[10];
#pragma unroll
    for (int n = 0; n < 10; n++) {
        rx[n] = sd[lp][3*n]; ry[n] = sd[lp][3*n+1]; rz[n] = sd[lp][3*n+2];
        off[n] = soff[lp][n];
    }
    int c4 = t * 4;
    float4 center = *(const float4*)(feat + (long)pt * F + c4);
    float4 acc = make_float4(0.f, 0.f, 0.f, 0.f);
#pragma unroll
    for (int s = 0; s < 7; s++) {
        int col = s * C + c4;
        float4 dx = *(const float4*)(dirn + col);
        float4 dy = *(const float4*)(dirn + W + col);
        float4 dz = *(const float4*)(dirn + 2 * W + col);
        float4 m = make_float4(-1e30f, -1e30f, -1e30f, -1e30f);
#pragma unroll
        for (int n = 0; n < 10; n++) {
            float4 f = *(const float4*)(feat + off[n] + col);
            m.x = fmaxf(m.x, silu_unit(rx[n]*dx.x + ry[n]*dy.x + rz[n]*dz.x) * f.x);
            m.y = fmaxf(m.y, silu_unit(rx[n]*dx.y + ry[n]*dy.y + rz[n]*dz.y) * f.y);
            m.z = fmaxf(m.z, silu_unit(rx[n]*dx.z + ry[n]*dy.z + rz[n]*dz.z) * f.z);
            m.w = fmaxf(m.w, silu_unit(rx[n]*dx.w + ry[n]*dy.w + rz[n]*dz.w) * f.w);
        }
        acc.x += m.x; acc.y += m.y; acc.z += m.z; acc.w += m.w;
    }
    float4 o;
    o.x = center.x + acc.x; o.y = center.y + acc.y;
    o.z = center.z + acc.z; o.w = center.w + acc.w;
    *(float4*)(out + (long)pt * C + c4) = o;
}

// ---------------------------------------------------------------------------
// BatchNorm stats, single launch: partial sums + last-block finish
// ---------------------------------------------------------------------------
__global__ void bn_stats_kernel(const float* __restrict__ X, int R, int C,
                                float* __restrict__ ps, float* __restrict__ ps2,
                                float* __restrict__ mean, float* __restrict__ rstd) {
    int lane = threadIdx.x & 31;
    int w = threadIdx.x >> 5;
    int c = blockIdx.x * 32 + lane;
    int chunk = blockIdx.y;
    int rowsPer = R >> 4;
    int r0 = chunk * rowsPer;
    float s = 0.0f, s2 = 0.0f;
    for (int r = r0 + w; r < r0 + rowsPer; r += 8) {
        float v = X[(long)r * C + c];
        s += v; s2 += v * v;
    }
    __shared__ float sh[8][32], sh2[8][32];
    sh[w][lane] = s; sh2[w][lane] = s2;
    __syncthreads();
    if (w == 0) {
#pragma unroll
        for (int i = 1; i < 8; i++) { s += sh[i][lane]; s2 += sh2[i][lane]; }
        ps [chunk * C + c] = s;
        ps2[chunk * C + c] = s2;
    }
    __shared__ bool isLast;
    __threadfence();
    __syncthreads();
    if (threadIdx.x == 0) {
        unsigned total = gridDim.x * gridDim.y;
        unsigned old = atomicAdd(&g_bn_ctr, 1u);
        isLast = (old == total - 1);
    }
    __syncthreads();
    if (isLast) {
        int cc = threadIdx.x;
        if (cc < C) {
            float ts = 0.0f, ts2 = 0.0f;
#pragma unroll
            for (int k = 0; k < 16; k++) { ts += ps[k * C + cc]; ts2 += ps2[k * C + cc]; }
            float m = ts / (float)R;
            float var = ts2 / (float)R - m * m;
            mean[cc] = m;
            rstd[cc] = rsqrtf(var + 1e-5f);
        }
        __syncthreads();
        if (threadIdx.x == 0) g_bn_ctr = 0;
    }
}

__global__ void bn_apply_silu_kernel(const float* __restrict__ X,
                                     const float* __restrict__ mean, const float* __restrict__ rstd,
                                     const float* __restrict__ g, const float* __restrict__ bb,
                                     float* __restrict__ Y, int total, int C) {
    int i = blockIdx.x * 256 + threadIdx.x;
    if (i >= total) return;
    int c = i & (C - 1);
    float y = (X[i] - mean[c]) * rstd[c] * g[c] + bb[c];
    Y[i] = silu_full(y);
}

// ---------------------------------------------------------------------------
// Fused 4-NN max-pool + permutation gather (float4)
// ---------------------------------------------------------------------------
template <int C>
__global__ void pool_gather_kernel(const float* __restrict__ fm, const int* __restrict__ idx4,
                                   const int* __restrict__ perm, const float* __restrict__ vin,
                                   float* __restrict__ fout, float* __restrict__ vout,
                                   int Nin, int Pout) {
    int bp = blockIdx.x;
    int b = bp / Pout;
    int p = bp - b * Pout;
    int t = threadIdx.x;
    __shared__ int si;
    __shared__ int sj[4];
    if (t == 0) si = perm[p];
    __syncthreads();
    if (t < 4) sj[t] = idx4[((long)b * Nin + si) * 4 + t];
    __syncthreads();
    float4 m = make_float4(-1e30f, -1e30f, -1e30f, -1e30f);
#pragma unroll
    for (int n = 0; n < 4; n++) {
        float4 f = *(const float4*)(fm + ((long)b * Nin + sj[n]) * C + t * 4);
        m.x = fmaxf(m.x, f.x); m.y = fmaxf(m.y, f.y);
        m.z = fmaxf(m.z, f.z); m.w = fmaxf(m.w, f.w);
    }
    *(float4*)(fout + (long)bp * C + t * 4) = m;
    if (t == 0) {
        vout[(long)bp * 3 + 0] = vin[((long)b * Nin + si) * 3 + 0];
        vout[(long)bp * 3 + 1] = vin[((long)b * Nin + si) * 3 + 1];
        vout[(long)bp * 3 + 2] = vin[((long)b * Nin + si) * 3 + 2];
    }
}

// ---------------------------------------------------------------------------
// Fused nearest (v1 and v2) — smem-staged sources, thread-per-query.
// ---------------------------------------------------------------------------
__global__ void nearest_both_kernel(const float* __restrict__ x,
                                    const float* __restrict__ v1,
                                    const float* __restrict__ v2,
                                    int* __restrict__ n1, int* __restrict__ n2) {
    __shared__ float sx1[NP1], sy1[NP1], sz1[NP1], sq1[NP1];
    __shared__ float sx2[NP2], sy2[NP2], sz2[NP2], sq2[NP2];
    int tid = threadIdx.x;
    int q = blockIdx.x * 64 + tid;
    int b = q >> 12;
    const float* p1 = v1 + (long)b * NP1 * 3;
    const float* p2 = v2 + (long)b * NP2 * 3;
    for (int j = tid; j < NP1; j += 64) {
        float a = p1[j * 3], c = p1[j * 3 + 1], d = p1[j * 3 + 2];
        sx1[j] = a; sy1[j] = c; sz1[j] = d; sq1[j] = a * a + c * c + d * d;
    }
    for (int j = tid; j < NP2; j += 64) {
        float a = p2[j * 3], c = p2[j * 3 + 1], d = p2[j * 3 + 2];
        sx2[j] = a; sy2[j] = c; sz2[j] = d; sq2[j] = a * a + c * c + d * d;
    }
    __syncthreads();
    float px = x[q * 3], py = x[q * 3 + 1], pz = x[q * 3 + 2];
    float pq = px * px + py * py + pz * pz;
    float best = 1e30f; int bj = 0;
    for (int j = 0; j < NP1; j++) {
        float dist = pq + sq1[j] - 2.0f * (px * sx1[j] + py * sy1[j] + pz * sz1[j]);
        if (dist < best) { best = dist; bj = j; }
    }
    n1[q] = bj;
    best = 1e30f; bj = 0;
    for (int j = 0; j < NP2; j++) {
        float dist = pq + sq2[j] - 2.0f * (px * sx2[j] + py * sy2[j] + pz * sz2[j]);
        if (dist < best) { best = dist; bj = j; }
    }
    n2[q] = bj;
}

// ---------------------------------------------------------------------------
// Final concat + upsample (float4)
// ---------------------------------------------------------------------------
__global__ void assemble_kernel(const float* __restrict__ fm0, const float* __restrict__ fm1,
                                const float* __restrict__ fm2, const float* __restrict__ fm3,
                                const float* __restrict__ fm4,
                                const int* __restrict__ n1, const int* __restrict__ n2,
                                float* __restrict__ out) {
    int pt = blockIdx.x;
    int b = pt >> 12;
    int j1 = n1[pt];
    int j2 = n2[pt];
    const float4* s0 = (const float4*)(fm0 + (long)pt * 128);
    const float4* s1 = (const float4*)(fm1 + (long)pt * 128);
    const float4* s2 = (const float4*)(fm2 + ((long)b * NP1 + j1) * 256);
    const float4* s3 = (const float4*)(fm3 + ((long)b * NP1 + j1) * 256);
    const float4* s4 = (const float4*)(fm4 + ((long)b * NP2 + j2) * 512);
    float4* o = (float4*)(out + (long)pt * 1280);
    for (int c = threadIdx.x; c < 320; c += 256) {
        float4 v;
        if (c < 32)       v = s0[c];
        else if (c < 64)  v = s1[c - 32];
        else if (c < 128) v = s2[c - 64];
        else if (c < 192) v = s3[c - 128];
        else              v = s4[c - 192];
        o[c] = v;
    }
}

// ---------------------------------------------------------------------------
// Host driver
// ---------------------------------------------------------------------------
extern "C" void kernel_launch(void* const* d_in, const int* in_sizes, int n_in,
                              void* d_out, int out_size) {
    const float* x    = (const float*)d_in[0];
    const float* d0   = (const float*)d_in[1];
    const float* w1   = (const float*)d_in[2];
    const float* b1   = (const float*)d_in[3];
    const float* dir1 = (const float*)d_in[4];
    const float* g1   = (const float*)d_in[5];
    const float* bb1  = (const float*)d_in[6];
    const float* w2   = (const float*)d_in[7];
    const float* b2   = (const float*)d_in[8];
    const float* dir2 = (const float*)d_in[9];
    const float* g2   = (const float*)d_in[10];
    const float* bb2  = (const float*)d_in[11];
    const float* w3   = (const float*)d_in[12];
    const float* b3   = (const float*)d_in[13];
    const float* dir3 = (const float*)d_in[14];
    const float* g3   = (const float*)d_in[15];
    const float* bb3  = (const float*)d_in[16];
    const float* w4   = (const float*)d_in[17];
    const float* b4   = (const float*)d_in[18];
    const float* dir4 = (const float*)d_in[19];
    const int* perm1  = (const int*)d_in[20];
    const int* perm2  = (const int*)d_in[21];
    float* out = (float*)d_out;

    float *d0n, *dir1n, *dir2n, *dir3n, *dir4n;
    int *idx10_0, *idx4_0, *idx10_1, *idx4_1, *idx10_2, *n1, *n2;
    float *dirs0, *dirs1, *dirs2;
    float *fm0, *feat1, *conv1, *fm1, *v1, *f1;
    float *feat2, *conv2, *fm2, *feat3, *conv3, *fm3;
    float *v2, *f2, *feat4, *fm4, *mean, *rstd, *bnp1, *bnp2;

    cudaGetSymbolAddress((void**)&d0n,  g_d0n);
    cudaGetSymbolAddress((void**)&dir1n, g_dir1n);
    cudaGetSymbolAddress((void**)&dir2n, g_dir2n);
    cudaGetSymbolAddress((void**)&dir3n, g_dir3n);
    cudaGetSymbolAddress((void**)&dir4n, g_dir4n);
    cudaGetSymbolAddress((void**)&idx10_0, g_idx10_0);
    cudaGetSymbolAddress((void**)&idx4_0,  g_idx4_0);
    cudaGetSymbolAddress((void**)&dirs0,   g_dirs0);
    cudaGetSymbolAddress((void**)&fm0,     g_fm0);
    cudaGetSymbolAddress((void**)&feat1,   g_feat1);
    cudaGetSymbolAddress((void**)&conv1,   g_conv1);
    cudaGetSymbolAddress((void**)&fm1,     g_fm1);
    cudaGetSymbolAddress((void**)&v1,      g_v1);
    cudaGetSymbolAddress((void**)&f1,      g_f1);
    cudaGetSymbolAddress((void**)&idx10_1, g_idx10_1);
    cudaGetSymbolAddress((void**)&idx4_1,  g_idx4_1);
    cudaGetSymbolAddress((void**)&dirs1,   g_dirs1);
    cudaGetSymbolAddress((void**)&feat2,   g_feat2);
    cudaGetSymbolAddress((void**)&conv2,   g_conv2);
    cudaGetSymbolAddress((void**)&fm2,     g_fm2);
    cudaGetSymbolAddress((void**)&feat3,   g_feat3);
    cudaGetSymbolAddress((void**)&conv3,   g_conv3);
    cudaGetSymbolAddress((void**)&fm3,     g_fm3);
    cudaGetSymbolAddress((void**)&v2,      g_v2);
    cudaGetSymbolAddress((void**)&f2,      g_f2);
    cudaGetSymbolAddress((void**)&idx10_2, g_idx10_2);
    cudaGetSymbolAddress((void**)&dirs2,   g_dirs2);
    cudaGetSymbolAddress((void**)&feat4,   g_feat4);
    cudaGetSymbolAddress((void**)&fm4,     g_fm4);
    cudaGetSymbolAddress((void**)&n1,      g_n1);
    cudaGetSymbolAddress((void**)&n2,      g_n2);
    cudaGetSymbolAddress((void**)&mean,    g_mean);
    cudaGetSymbolAddress((void**)&rstd,    g_rstd);
    cudaGetSymbolAddress((void**)&bnp1,    g_bnp1);
    cudaGetSymbolAddress((void**)&bnp2,    g_bnp2);

    // ---- Level 0 (V = 4096) ----  (index 3 = gemm1 -> profiled: revert check)
    norm_all_kernel<<<35, 256>>>(d0, dir1, dir2, dir3, dir4,
                                 d0n, dir1n, dir2n, dir3n, dir4n);           // 0
    knn_warp_kernel<<<BATCH * NV / 8, 256>>>(x, NV, idx10_0, idx4_0, dirs0); // 1
    conv_surface_kernel<<<BATCH * NV / 4, 128>>>(dirs0, d0n, fm0);           // 2
    gemm_tf32_kernel<<<dim3(1024 / 128, (BATCH * NV) / 128), 256>>>(fm0, w1, b1, feat1, BATCH * NV, 1024, 128); // 3 <-- profiled
    conv_layer_kernel<128, 4><<<BATCH * NV / 4, 128>>>(feat1, dirs0, idx10_0, dir1n, conv1, NV);
    bn_stats_kernel<<<dim3(128 / 32, 16), 256>>>(conv1, BATCH * NV, 128, bnp1, bnp2, mean, rstd);
    bn_apply_silu_kernel<<<(BATCH * NV * 128 + 255) / 256, 256>>>(conv1, mean, rstd, g1, bb1, fm1, BATCH * NV * 128, 128);
    pool_gather_kernel<128><<<BATCH * NP1, 32>>>(fm1, idx4_0, perm1, x, f1, v1, NV, NP1);

    // ---- Level 1 (V = 1024) ----
    knn_warp_kernel<<<BATCH * NP1 / 8, 256>>>(v1, NP1, idx10_1, idx4_1, dirs1);
    gemm_tf32_kernel<<<dim3(2048 / 128, (BATCH * NP1) / 128), 256>>>(f1, w2, b2, feat2, BATCH * NP1, 2048, 128);
    conv_layer_kernel<256, 2><<<BATCH * NP1 / 2, 128>>>(feat2, dirs1, idx10_1, dir2n, conv2, NP1);
    bn_stats_kernel<<<dim3(256 / 32, 16), 256>>>(conv2, BATCH * NP1, 256, bnp1, bnp2, mean, rstd);
    bn_apply_silu_kernel<<<(BATCH * NP1 * 256 + 255) / 256, 256>>>(conv2, mean, rstd, g2, bb2, fm2, BATCH * NP1 * 256, 256);
    gemm_tf32_kernel<<<dim3(2048 / 128, (BATCH * NP1) / 128), 256>>>(fm2, w3, b3, feat3, BATCH * NP1, 2048, 256);
    conv_layer_kernel<256, 2><<<BATCH * NP1 / 2, 128>>>(feat3, dirs1, idx10_1, dir3n, conv3, NP1);
    bn_stats_kernel<<<dim3(256 / 32, 16), 256>>>(conv3, BATCH * NP1, 256, bnp1, bnp2, mean, rstd);
    bn_apply_silu_kernel<<<(BATCH * NP1 * 256 + 255) / 256, 256>>>(conv3, mean, rstd, g3, bb3, fm3, BATCH * NP1 * 256, 256);
    pool_gather_kernel<256><<<BATCH * NP2, 64>>>(fm3, idx4_1, perm2, v1, f2, v2, NP1, NP2);

    // ---- Level 2 (V = 256) ----
    knn_warp_kernel<<<BATCH * NP2 / 8, 256>>>(v2, NP2, idx10_2, (int*)0, dirs2);
    gemm_tf32_kernel<<<dim3(4096 / 128, (BATCH * NP2) / 128), 256>>>(f2, w4, b4, feat4, BATCH * NP2, 4096, 256);
    conv_layer_kernel<512, 2><<<BATCH * NP2 / 2, 256>>>(feat4, dirs2, idx10_2, dir4n, fm4, NP2);

    // ---- Upsample + concat ----
    nearest_both_kernel<<<BATCH * NV / 64, 64>>>(x, v1, v2, n1, n2);
    assemble_kernel<<<BATCH * NV, 256>>>(fm0, fm1, fm2, fm3, fm4, n1, n2, out);
}

// round 15
// speedup vs baseline: 1.5039x; 1.0745x over previous
#include <cuda_runtime.h>
#include <math.h>

#define BATCH 2
#define NV    4096
#define NP1   1024
#define NP2   256
#define FULLM 0xffffffffu

// ---------------------------------------------------------------------------
// Device scratch
// ---------------------------------------------------------------------------
__device__ float g_d0n  [3*896];
__device__ float g_dir1n[3*896];
__device__ float g_dir2n[3*1792];
__device__ float g_dir3n[3*1792];
__device__ float g_dir4n[3*3584];

__device__ int   g_idx10_0[BATCH*NV*10];
__device__ int   g_idx4_0 [BATCH*NV*4];
__device__ float g_dirs0  [BATCH*NV*10*3];
__device__ float g_fm0    [BATCH*NV*128];
__device__ float g_feat1  [BATCH*NV*1024];
__device__ float g_conv1  [BATCH*NV*128];
__device__ float g_fm1    [BATCH*NV*128];

__device__ float g_v1 [BATCH*NP1*3];
__device__ float g_f1 [BATCH*NP1*128];
__device__ int   g_idx10_1[BATCH*NP1*10];
__device__ int   g_idx4_1 [BATCH*NP1*4];
__device__ float g_dirs1  [BATCH*NP1*10*3];
__device__ float g_feat2  [BATCH*NP1*2048];
__device__ float g_conv2  [BATCH*NP1*256];
__device__ float g_fm2    [BATCH*NP1*256];
__device__ float g_feat3  [BATCH*NP1*2048];
__device__ float g_conv3  [BATCH*NP1*256];
__device__ float g_fm3    [BATCH*NP1*256];

__device__ float g_v2 [BATCH*NP2*3];
__device__ float g_f2 [BATCH*NP2*256];
__device__ int   g_idx10_2[BATCH*NP2*10];
__device__ float g_dirs2  [BATCH*NP2*10*3];
__device__ float g_feat4  [BATCH*NP2*4096];
__device__ float g_fm4    [BATCH*NP2*512];

__device__ int   g_n1[BATCH*NV];
__device__ int   g_n2[BATCH*NV];
__device__ float g_mean[512];
__device__ float g_rstd[512];
__device__ float g_bnp1[16*256];
__device__ float g_bnp2[16*256];
__device__ unsigned g_bn_ctr = 0;

// ---------------------------------------------------------------------------
// Math helpers
// ---------------------------------------------------------------------------
__device__ __forceinline__ float silu_unit(float y) {
    float u = y * y;
    float p = fmaf(u, 2.1357672e-5f, -2.1081349e-4f);
    p = fmaf(u, p, 2.0833333e-3f);
    p = fmaf(u, p, -2.0833333e-2f);
    p = fmaf(u, p, 0.25f);
    float s = fmaf(y, p, 0.5f);
    return y * s;
}

__device__ __forceinline__ float silu_full(float y) {
    return y / (1.0f + __expf(-y));
}

__device__ __forceinline__ float to_tf32(float x) {
    float r;
    asm("cvt.rna.tf32.f32 %0, %1;" : "=f"(r) : "f"(x));
    return r;
}

__device__ __forceinline__ void mma_tf32(float* c, const float* a, const float* b) {
    asm volatile(
        "mma.sync.aligned.m16n8k8.row.col.f32.tf32.tf32.f32 "
        "{%0,%1,%2,%3}, {%4,%5,%6,%7}, {%8,%9}, {%0,%1,%2,%3};"
        : "+f"(c[0]), "+f"(c[1]), "+f"(c[2]), "+f"(c[3])
        : "r"(__float_as_uint(a[0])), "r"(__float_as_uint(a[1])),
          "r"(__float_as_uint(a[2])), "r"(__float_as_uint(a[3])),
          "r"(__float_as_uint(b[0])), "r"(__float_as_uint(b[1])));
}

// ---------------------------------------------------------------------------
// Fused column-normalize of all 5 direction matrices
// ---------------------------------------------------------------------------
__global__ void norm_all_kernel(const float* __restrict__ d0, const float* __restrict__ dir1,
                                const float* __restrict__ dir2, const float* __restrict__ dir3,
                                const float* __restrict__ dir4,
                                float* __restrict__ o0, float* __restrict__ o1,
                                float* __restrict__ o2, float* __restrict__ o3,
                                float* __restrict__ o4) {
    int c = blockIdx.x * 256 + threadIdx.x;
    if (c >= 8960) return;
    const float* S; float* D; int W, col;
    if (c < 896)       { S = d0;   D = o0; W = 896;  col = c; }
    else if (c < 1792) { S = dir1; D = o1; W = 896;  col = c - 896; }
    else if (c < 3584) { S = dir2; D = o2; W = 1792; col = c - 1792; }
    else if (c < 5376) { S = dir3; D = o3; W = 1792; col = c - 3584; }
    else               { S = dir4; D = o4; W = 3584; col = c - 5376; }
    float x = S[col], y = S[W + col], z = S[2 * W + col];
    float n = sqrtf(x * x + y * y + z * z);
    float r = 1.0f / fmaxf(n, 1e-12f);
    D[col] = x * r; D[W + col] = y * r; D[2 * W + col] = z * r;
}

// ---------------------------------------------------------------------------
// Warp-cooperative exact kNN (k=10 + self), fused unit-direction output.
// ---------------------------------------------------------------------------
__global__ void knn_warp_kernel(const float* __restrict__ v, int N,
                                int* __restrict__ idx10, int* __restrict__ idx4,
                                float* __restrict__ dirs) {
    const int t = threadIdx.x;
    const int wid = t >> 5;
    const int lane = t & 31;
    const int q = blockIdx.x * 8 + wid;
    const int b = q / N;
    const int i = q - b * N;
    const float* vb = v + (long)b * N * 3;
    const float px = vb[i * 3 + 0], py = vb[i * 3 + 1], pz = vb[i * 3 + 2];
    const float pq = px * px + py * py + pz * pz;

    unsigned long long lst = 0xFFFFFFFFFFFFFFFFull;
    unsigned long long kmax_r = 0xFFFFFFFFFFFFFFFFull;

    __shared__ float sx[256], sy[256], sz[256], sq[256];

    for (int j0 = 0; j0 < N; j0 += 256) {
        __syncthreads();
        {
            int j = j0 + t;
            float cx = vb[j * 3 + 0];
            float cy = vb[j * 3 + 1];
            float cz = vb[j * 3 + 2];
            sx[t] = cx; sy[t] = cy; sz[t] = cz;
            sq[t] = cx * cx + cy * cy + cz * cz;
        }
        __syncthreads();
#pragma unroll
        for (int s = 0; s < 8; s++) {
            int jj = s * 32 + lane;
            float dot = px * sx[jj] + py * sy[jj] + pz * sz[jj];
            float dist = pq + sq[jj] - 2.0f * dot;
            unsigned bits = __float_as_uint(dist);
            unsigned u = bits ^ ((unsigned)((int)bits >> 31) | 0x80000000u);
            unsigned long long mykey =
                ((unsigned long long)u << 32) | (unsigned)(j0 + jj);
            unsigned ball = __ballot_sync(FULLM, mykey < kmax_r);
            while (ball) {
                int src = __ffs(ball) - 1;
                ball &= ball - 1;
                unsigned long long cand = __shfl_sync(FULLM, mykey, src);
                if (cand < kmax_r) {
                    unsigned below = __ballot_sync(FULLM, lst < cand);
                    int pos = __popc(below);
                    unsigned long long sh = __shfl_up_sync(FULLM, lst, 1);
                    if (lane < 11) {
                        if (lane == pos) lst = cand;
                        else if (lane > pos) lst = sh;
                    }
                    kmax_r = __shfl_sync(FULLM, lst, 10);
                }
            }
        }
    }

    int myidx = (int)(unsigned)(lst & 0xFFFFFFFFull);
    if (lane >= 1 && lane <= 10) {
        idx10[(long)q * 10 + (lane - 1)] = myidx;
        if (idx4 != 0 && lane <= 4)
            idx4[(long)q * 4 + (lane - 1)] = myidx;
        float dx = vb[myidx * 3 + 0] - px;
        float dy = vb[myidx * 3 + 1] - py;
        float dz = vb[myidx * 3 + 2] - pz;
        float nn = sqrtf(dx * dx + dy * dy + dz * dz);
        float r = 1.0f / fmaxf(nn, 1e-12f);
        dirs[(long)q * 30 + (lane - 1) * 3 + 0] = dx * r;
        dirs[(long)q * 30 + (lane - 1) * 3 + 1] = dy * r;
        dirs[(long)q * 30 + (lane - 1) * 3 + 2] = dz * r;
    }
}

// ---------------------------------------------------------------------------
// conv_surface, float4, monotone-SiLU hoist (R10 config: 32 thr/point-block)
// ---------------------------------------------------------------------------
__global__ void conv_surface_kernel(const float* __restrict__ dirs,
                                    const float* __restrict__ dn,
                                    float* __restrict__ fm0) {
    int pt = blockIdx.x;
    int t = threadIdx.x;
    __shared__ float sd[30];
    if (t < 30) sd[t] = dirs[(long)pt * 30 + t];
    __syncwarp();
    float rx[10], ry[10], rz[10];
#pragma unroll
    for (int n = 0; n < 10; n++) { rx[n] = sd[3*n]; ry[n] = sd[3*n+1]; rz[n] = sd[3*n+2]; }
    int c4 = t * 4;
    float4 acc = make_float4(0.f, 0.f, 0.f, 0.f);
#pragma unroll
    for (int s = 0; s < 7; s++) {
        int col = s * 128 + c4;
        float4 dx = *(const float4*)(dn + col);
        float4 dy = *(const float4*)(dn + 896 + col);
        float4 dz = *(const float4*)(dn + 1792 + col);
        float4 m = make_float4(-1e30f, -1e30f, -1e30f, -1e30f);
#pragma unroll
        for (int n = 0; n < 10; n++) {
            m.x = fmaxf(m.x, rx[n]*dx.x + ry[n]*dy.x + rz[n]*dz.x);
            m.y = fmaxf(m.y, rx[n]*dx.y + ry[n]*dy.y + rz[n]*dz.y);
            m.z = fmaxf(m.z, rx[n]*dx.z + ry[n]*dy.z + rz[n]*dz.z);
            m.w = fmaxf(m.w, rx[n]*dx.w + ry[n]*dy.w + rz[n]*dz.w);
        }
        acc.x += silu_unit(m.x);
        acc.y += silu_unit(m.y);
        acc.z += silu_unit(m.z);
        acc.w += silu_unit(m.w);
    }
    float4 o;
    o.x = silu_full(acc.x); o.y = silu_full(acc.y);
    o.z = silu_full(acc.z); o.w = silu_full(acc.w);
    *(float4*)(fm0 + (long)pt * 128 + c4) = o;
}

// ---------------------------------------------------------------------------
// TF32 tensor-core GEMM with bias (R10 config: 128x128 tile, warp 64x32)
// ---------------------------------------------------------------------------
__global__ __launch_bounds__(256, 2)
void gemm_tf32_kernel(const float* __restrict__ A, const float* __restrict__ B,
                      const float* __restrict__ bias, float* __restrict__ C,
                      int M, int N, int K) {
    __shared__ float As[2][128][20];
    __shared__ float Bs[2][16][136];
    const int tid = threadIdx.x;
    const int warp = tid >> 5, lane = tid & 31;
    const int bm = blockIdx.y * 128;
    const int bn = blockIdx.x * 128;
    const int wr = (warp & 1) * 64;
    const int wc = (warp >> 1) * 32;

    const int arow = tid >> 1;
    const int akb  = (tid & 1) * 8;
    const int brow = tid >> 4;
    const int bcb  = (tid & 15) * 8;

    const float* Ag = A + (long)(bm + arow) * K + akb;
    const float* Bg = B + (long)brow * N + bn + bcb;

    float acc[4][4][4];
#pragma unroll
    for (int mi = 0; mi < 4; mi++)
#pragma unroll
        for (int ni = 0; ni < 4; ni++)
#pragma unroll
            for (int r = 0; r < 4; r++) acc[mi][ni][r] = 0.0f;

    const int T = K >> 4;

    {
        float4 a0 = *(const float4*)(Ag);
        float4 a1 = *(const float4*)(Ag + 4);
        float4 b0 = *(const float4*)(Bg);
        float4 b1 = *(const float4*)(Bg + 4);
        As[0][arow][akb + 0] = to_tf32(a0.x); As[0][arow][akb + 1] = to_tf32(a0.y);
        As[0][arow][akb + 2] = to_tf32(a0.z); As[0][arow][akb + 3] = to_tf32(a0.w);
        As[0][arow][akb + 4] = to_tf32(a1.x); As[0][arow][akb + 5] = to_tf32(a1.y);
        As[0][arow][akb + 6] = to_tf32(a1.z); As[0][arow][akb + 7] = to_tf32(a1.w);
        Bs[0][brow][bcb + 0] = to_tf32(b0.x); Bs[0][brow][bcb + 1] = to_tf32(b0.y);
        Bs[0][brow][bcb + 2] = to_tf32(b0.z); Bs[0][brow][bcb + 3] = to_tf32(b0.w);
        Bs[0][brow][bcb + 4] = to_tf32(b1.x); Bs[0][brow][bcb + 5] = to_tf32(b1.y);
        Bs[0][brow][bcb + 6] = to_tf32(b1.z); Bs[0][brow][bcb + 7] = to_tf32(b1.w);
    }
    __syncthreads();

    const int lr = lane >> 2;
    const int lc = lane & 3;

    for (int t = 0; t < T; t++) {
        const int cur = t & 1;
        float4 a0, a1, b0, b1;
        if (t + 1 < T) {
            a0 = *(const float4*)(Ag + (t + 1) * 16);
            a1 = *(const float4*)(Ag + (t + 1) * 16 + 4);
            b0 = *(const float4*)(Bg + (long)(t + 1) * 16 * N);
            b1 = *(const float4*)(Bg + (long)(t + 1) * 16 * N + 4);
        }
#pragma unroll
        for (int kk = 0; kk < 16; kk += 8) {
            float af[4][4], bf[4][2];
#pragma unroll
            for (int mi = 0; mi < 4; mi++) {
                int r0 = wr + mi * 16 + lr;
                af[mi][0] = As[cur][r0][kk + lc];
                af[mi][1] = As[cur][r0 + 8][kk + lc];
                af[mi][2] = As[cur][r0][kk + lc + 4];
                af[mi][3] = As[cur][r0 + 8][kk + lc + 4];
            }
#pragma unroll
            for (int ni = 0; ni < 4; ni++) {
                int cb = wc + ni * 8 + lr;
                bf[ni][0] = Bs[cur][kk + lc][cb];
                bf[ni][1] = Bs[cur][kk + lc + 4][cb];
            }
#pragma unroll
            for (int mi = 0; mi < 4; mi++)
#pragma unroll
                for (int ni = 0; ni < 4; ni++)
                    mma_tf32(acc[mi][ni], af[mi], bf[ni]);
        }
        if (t + 1 < T) {
            const int nxt = cur ^ 1;
            As[nxt][arow][akb + 0] = to_tf32(a0.x); As[nxt][arow][akb + 1] = to_tf32(a0.y);
            As[nxt][arow][akb + 2] = to_tf32(a0.z); As[nxt][arow][akb + 3] = to_tf32(a0.w);
            As[nxt][arow][akb + 4] = to_tf32(a1.x); As[nxt][arow][akb + 5] = to_tf32(a1.y);
            As[nxt][arow][akb + 6] = to_tf32(a1.z); As[nxt][arow][akb + 7] = to_tf32(a1.w);
            Bs[nxt][brow][bcb + 0] = to_tf32(b0.x); Bs[nxt][brow][bcb + 1] = to_tf32(b0.y);
            Bs[nxt][brow][bcb + 2] = to_tf32(b0.z); Bs[nxt][brow][bcb + 3] = to_tf32(b0.w);
            Bs[nxt][brow][bcb + 4] = to_tf32(b1.x); Bs[nxt][brow][bcb + 5] = to_tf32(b1.y);
            Bs[nxt][brow][bcb + 6] = to_tf32(b1.z); Bs[nxt][brow][bcb + 7] = to_tf32(b1.w);
            __syncthreads();
        }
    }

#pragma unroll
    for (int mi = 0; mi < 4; mi++) {
        int row0 = bm + wr + mi * 16 + lr;
#pragma unroll
        for (int ni = 0; ni < 4; ni++) {
            int col = bn + wc + ni * 8 + lc * 2;
            float bx = bias[col], by = bias[col + 1];
            float2 o0, o1;
            o0.x = acc[mi][ni][0] + bx; o0.y = acc[mi][ni][1] + by;
            o1.x = acc[mi][ni][2] + bx; o1.y = acc[mi][ni][3] + by;
            *(float2*)(C + (long)row0 * N + col)       = o0;
            *(float2*)(C + (long)(row0 + 8) * N + col) = o1;
        }
    }
}

// ---------------------------------------------------------------------------
// conv_layer, float4 (R10 config: C/4 threads per point-block)
// ---------------------------------------------------------------------------
template <int C>
__global__ void conv_layer_kernel(const float* __restrict__ feat,
                                  const float* __restrict__ dirs,
                                  const int* __restrict__ idx,
                                  const float* __restrict__ dirn,
                                  float* __restrict__ out, int Npts) {
    const int F = 8 * C;
    const int W = 7 * C;
    int pt = blockIdx.x;
    int b = pt / Npts;
    int t = threadIdx.x;
    __shared__ float sd[30];
    __shared__ int soff[10];
    if (t < 10) {
        int j = idx[(long)pt * 10 + t];
        soff[t] = (b * Npts + j) * F + C;
    }
    if (t < 30) sd[t] = dirs[(long)pt * 30 + t];
    __syncthreads();
    float rx[10], ry[10], rz[10];
    int off[10];
#pragma unroll
    for (int n = 0; n < 10; n++) {
        rx[n] = sd[3*n]; ry[n] = sd[3*n+1]; rz[n] = sd[3*n+2];
        off[n] = soff[n];
    }
    int c4 = t * 4;
    float4 center = *(const float4*)(feat + (long)pt * F + c4);
    float4 acc = make_float4(0.f, 0.f, 0.f, 0.f);
#pragma unroll
    for (int s = 0; s < 7; s++) {
        int col = s * C + c4;
        float4 dx = *(const float4*)(dirn + col);
        float4 dy = *(const float4*)(dirn + W + col);
        float4 dz = *(const float4*)(dirn + 2 * W + col);
        float4 m = make_float4(-1e30f, -1e30f, -1e30f, -1e30f);
#pragma unroll
        for (int n = 0; n < 10; n++) {
            float4 f = *(const float4*)(feat + off[n] + col);
            m.x = fmaxf(m.x, silu_unit(rx[n]*dx.x + ry[n]*dy.x + rz[n]*dz.x) * f.x);
            m.y = fmaxf(m.y, silu_unit(rx[n]*dx.y + ry[n]*dy.y + rz[n]*dz.y) * f.y);
            m.z = fmaxf(m.z, silu_unit(rx[n]*dx.z + ry[n]*dy.z + rz[n]*dz.z) * f.z);
            m.w = fmaxf(m.w, silu_unit(rx[n]*dx.w + ry[n]*dy.w + rz[n]*dz.w) * f.w);
        }
        acc.x += m.x; acc.y += m.y; acc.z += m.z; acc.w += m.w;
    }
    float4 o;
    o.x = center.x + acc.x; o.y = center.y + acc.y;
    o.z = center.z + acc.z; o.w = center.w + acc.w;
    *(float4*)(out + (long)pt * C + c4) = o;
}

// ---------------------------------------------------------------------------
// BatchNorm stats, single launch: partial sums + last-block finish
// ---------------------------------------------------------------------------
__global__ void bn_stats_kernel(const float* __restrict__ X, int R, int C,
                                float* __restrict__ ps, float* __restrict__ ps2,
                                float* __restrict__ mean, float* __restrict__ rstd) {
    int lane = threadIdx.x & 31;
    int w = threadIdx.x >> 5;
    int c = blockIdx.x * 32 + lane;
    int chunk = blockIdx.y;
    int rowsPer = R >> 4;
    int r0 = chunk * rowsPer;
    float s = 0.0f, s2 = 0.0f;
    for (int r = r0 + w; r < r0 + rowsPer; r += 8) {
        float v = X[(long)r * C + c];
        s += v; s2 += v * v;
    }
    __shared__ float sh[8][32], sh2[8][32];
    sh[w][lane] = s; sh2[w][lane] = s2;
    __syncthreads();
    if (w == 0) {
#pragma unroll
        for (int i = 1; i < 8; i++) { s += sh[i][lane]; s2 += sh2[i][lane]; }
        ps [chunk * C + c] = s;
        ps2[chunk * C + c] = s2;
    }
    __shared__ bool isLast;
    __threadfence();
    __syncthreads();
    if (threadIdx.x == 0) {
        unsigned total = gridDim.x * gridDim.y;
        unsigned old = atomicAdd(&g_bn_ctr, 1u);
        isLast = (old == total - 1);
    }
    __syncthreads();
    if (isLast) {
        int cc = threadIdx.x;
        if (cc < C) {
            float ts = 0.0f, ts2 = 0.0f;
#pragma unroll
            for (int k = 0; k < 16; k++) { ts += ps[k * C + cc]; ts2 += ps2[k * C + cc]; }
            float m = ts / (float)R;
            float var = ts2 / (float)R - m * m;
            mean[cc] = m;
            rstd[cc] = rsqrtf(var + 1e-5f);
        }
        __syncthreads();
        if (threadIdx.x == 0) g_bn_ctr = 0;
    }
}

__global__ void bn_apply_silu_kernel(const float* __restrict__ X,
                                     const float* __restrict__ mean, const float* __restrict__ rstd,
                                     const float* __restrict__ g, const float* __restrict__ bb,
                                     float* __restrict__ Y, int total, int C) {
    int i = blockIdx.x * 256 + threadIdx.x;
    if (i >= total) return;
    int c = i & (C - 1);
    float y = (X[i] - mean[c]) * rstd[c] * g[c] + bb[c];
    Y[i] = silu_full(y);
}

// ---------------------------------------------------------------------------
// Fused 4-NN max-pool + permutation gather (float4)
// ---------------------------------------------------------------------------
template <int C>
__global__ void pool_gather_kernel(const float* __restrict__ fm, const int* __restrict__ idx4,
                                   const int* __restrict__ perm, const float* __restrict__ vin,
                                   float* __restrict__ fout, float* __restrict__ vout,
                                   int Nin, int Pout) {
    int bp = blockIdx.x;
    int b = bp / Pout;
    int p = bp - b * Pout;
    int t = threadIdx.x;
    __shared__ int si;
    __shared__ int sj[4];
    if (t == 0) si = perm[p];
    __syncthreads();
    if (t < 4) sj[t] = idx4[((long)b * Nin + si) * 4 + t];
    __syncthreads();
    float4 m = make_float4(-1e30f, -1e30f, -1e30f, -1e30f);
#pragma unroll
    for (int n = 0; n < 4; n++) {
        float4 f = *(const float4*)(fm + ((long)b * Nin + sj[n]) * C + t * 4);
        m.x = fmaxf(m.x, f.x); m.y = fmaxf(m.y, f.y);
        m.z = fmaxf(m.z, f.z); m.w = fmaxf(m.w, f.w);
    }
    *(float4*)(fout + (long)bp * C + t * 4) = m;
    if (t == 0) {
        vout[(long)bp * 3 + 0] = vin[((long)b * Nin + si) * 3 + 0];
        vout[(long)bp * 3 + 1] = vin[((long)b * Nin + si) * 3 + 1];
        vout[(long)bp * 3 + 2] = vin[((long)b * Nin + si) * 3 + 2];
    }
}

// ---------------------------------------------------------------------------
// Fused nearest (v1 and v2) — smem-staged sources, thread-per-query.
// ---------------------------------------------------------------------------
__global__ void nearest_both_kernel(const float* __restrict__ x,
                                    const float* __restrict__ v1,
                                    const float* __restrict__ v2,
                                    int* __restrict__ n1, int* __restrict__ n2) {
    __shared__ float sx1[NP1], sy1[NP1], sz1[NP1], sq1[NP1];
    __shared__ float sx2[NP2], sy2[NP2], sz2[NP2], sq2[NP2];
    int tid = threadIdx.x;
    int q = blockIdx.x * 64 + tid;
    int b = q >> 12;
    const float* p1 = v1 + (long)b * NP1 * 3;
    const float* p2 = v2 + (long)b * NP2 * 3;
    for (int j = tid; j < NP1; j += 64) {
        float a = p1[j * 3], c = p1[j * 3 + 1], d = p1[j * 3 + 2];
        sx1[j] = a; sy1[j] = c; sz1[j] = d; sq1[j] = a * a + c * c + d * d;
    }
    for (int j = tid; j < NP2; j += 64) {
        float a = p2[j * 3], c = p2[j * 3 + 1], d = p2[j * 3 + 2];
        sx2[j] = a; sy2[j] = c; sz2[j] = d; sq2[j] = a * a + c * c + d * d;
    }
    __syncthreads();
    float px = x[q * 3], py = x[q * 3 + 1], pz = x[q * 3 + 2];
    float pq = px * px + py * py + pz * pz;
    float best = 1e30f; int bj = 0;
    for (int j = 0; j < NP1; j++) {
        float dist = pq + sq1[j] - 2.0f * (px * sx1[j] + py * sy1[j] + pz * sz1[j]);
        if (dist < best) { best = dist; bj = j; }
    }
    n1[q] = bj;
    best = 1e30f; bj = 0;
    for (int j = 0; j < NP2; j++) {
        float dist = pq + sq2[j] - 2.0f * (px * sx2[j] + py * sy2[j] + pz * sz2[j]);
        if (dist < best) { best = dist; bj = j; }
    }
    n2[q] = bj;
}

// ---------------------------------------------------------------------------
// Final concat + upsample (float4)
// ---------------------------------------------------------------------------
__global__ void assemble_kernel(const float* __restrict__ fm0, const float* __restrict__ fm1,
                                const float* __restrict__ fm2, const float* __restrict__ fm3,
                                const float* __restrict__ fm4,
                                const int* __restrict__ n1, const int* __restrict__ n2,
                                float* __restrict__ out) {
    int pt = blockIdx.x;
    int b = pt >> 12;
    int j1 = n1[pt];
    int j2 = n2[pt];
    const float4* s0 = (const float4*)(fm0 + (long)pt * 128);
    const float4* s1 = (const float4*)(fm1 + (long)pt * 128);
    const float4* s2 = (const float4*)(fm2 + ((long)b * NP1 + j1) * 256);
    const float4* s3 = (const float4*)(fm3 + ((long)b * NP1 + j1) * 256);
    const float4* s4 = (const float4*)(fm4 + ((long)b * NP2 + j2) * 512);
    float4* o = (float4*)(out + (long)pt * 1280);
    for (int c = threadIdx.x; c < 320; c += 256) {
        float4 v;
        if (c < 32)       v = s0[c];
        else if (c < 64)  v = s1[c - 32];
        else if (c < 128) v = s2[c - 64];
        else if (c < 192) v = s3[c - 128];
        else              v = s4[c - 192];
        o[c] = v;
    }
}

// ---------------------------------------------------------------------------
// Host driver with stream fork/join (graph-capturable cross-stream pattern)
// ---------------------------------------------------------------------------
static cudaStream_t g_s1 = 0, g_s2 = 0;
static cudaEvent_t  g_ev[8];
static bool g_streams_ready = false;

extern "C" void kernel_launch(void* const* d_in, const int* in_sizes, int n_in,
                              void* d_out, int out_size) {
    const float* x    = (const float*)d_in[0];
    const float* d0   = (const float*)d_in[1];
    const float* w1   = (const float*)d_in[2];
    const float* b1   = (const float*)d_in[3];
    const float* dir1 = (const float*)d_in[4];
    const float* g1   = (const float*)d_in[5];
    const float* bb1  = (const float*)d_in[6];
    const float* w2   = (const float*)d_in[7];
    const float* b2   = (const float*)d_in[8];
    const float* dir2 = (const float*)d_in[9];
    const float* g2   = (const float*)d_in[10];
    const float* bb2  = (const float*)d_in[11];
    const float* w3   = (const float*)d_in[12];
    const float* b3   = (const float*)d_in[13];
    const float* dir3 = (const float*)d_in[14];
    const float* g3   = (const float*)d_in[15];
    const float* bb3  = (const float*)d_in[16];
    const float* w4   = (const float*)d_in[17];
    const float* b4   = (const float*)d_in[18];
    const float* dir4 = (const float*)d_in[19];
    const int* perm1  = (const int*)d_in[20];
    const int* perm2  = (const int*)d_in[21];
    float* out = (float*)d_out;

    // One-time host-side setup (no device memory; device work identical per call)
    if (!g_streams_ready) {
        cudaStreamCreateWithFlags(&g_s1, cudaStreamNonBlocking);
        cudaStreamCreateWithFlags(&g_s2, cudaStreamNonBlocking);
        for (int e = 0; e < 8; e++)
            cudaEventCreateWithFlags(&g_ev[e], cudaEventDisableTiming);
        g_streams_ready = true;
    }

    float *d0n, *dir1n, *dir2n, *dir3n, *dir4n;
    int *idx10_0, *idx4_0, *idx10_1, *idx4_1, *idx10_2, *n1, *n2;
    float *dirs0, *dirs1, *dirs2;
    float *fm0, *feat1, *conv1, *fm1, *v1, *f1;
    float *feat2, *conv2, *fm2, *feat3, *conv3, *fm3;
    float *v2, *f2, *feat4, *fm4, *mean, *rstd, *bnp1, *bnp2;

    cudaGetSymbolAddress((void**)&d0n,  g_d0n);
    cudaGetSymbolAddress((void**)&dir1n, g_dir1n);
    cudaGetSymbolAddress((void**)&dir2n, g_dir2n);
    cudaGetSymbolAddress((void**)&dir3n, g_dir3n);
    cudaGetSymbolAddress((void**)&dir4n, g_dir4n);
    cudaGetSymbolAddress((void**)&idx10_0, g_idx10_0);
    cudaGetSymbolAddress((void**)&idx4_0,  g_idx4_0);
    cudaGetSymbolAddress((void**)&dirs0,   g_dirs0);
    cudaGetSymbolAddress((void**)&fm0,     g_fm0);
    cudaGetSymbolAddress((void**)&feat1,   g_feat1);
    cudaGetSymbolAddress((void**)&conv1,   g_conv1);
    cudaGetSymbolAddress((void**)&fm1,     g_fm1);
    cudaGetSymbolAddress((void**)&v1,      g_v1);
    cudaGetSymbolAddress((void**)&f1,      g_f1);
    cudaGetSymbolAddress((void**)&idx10_1, g_idx10_1);
    cudaGetSymbolAddress((void**)&idx4_1,  g_idx4_1);
    cudaGetSymbolAddress((void**)&dirs1,   g_dirs1);
    cudaGetSymbolAddress((void**)&feat2,   g_feat2);
    cudaGetSymbolAddress((void**)&conv2,   g_conv2);
    cudaGetSymbolAddress((void**)&fm2,     g_fm2);
    cudaGetSymbolAddress((void**)&feat3,   g_feat3);
    cudaGetSymbolAddress((void**)&conv3,   g_conv3);
    cudaGetSymbolAddress((void**)&fm3,     g_fm3);
    cudaGetSymbolAddress((void**)&v2,      g_v2);
    cudaGetSymbolAddress((void**)&f2,      g_f2);
    cudaGetSymbolAddress((void**)&idx10_2, g_idx10_2);
    cudaGetSymbolAddress((void**)&dirs2,   g_dirs2);
    cudaGetSymbolAddress((void**)&feat4,   g_feat4);
    cudaGetSymbolAddress((void**)&fm4,     g_fm4);
    cudaGetSymbolAddress((void**)&n1,      g_n1);
    cudaGetSymbolAddress((void**)&n2,      g_n2);
    cudaGetSymbolAddress((void**)&mean,    g_mean);
    cudaGetSymbolAddress((void**)&rstd,    g_rstd);
    cudaGetSymbolAddress((void**)&bnp1,    g_bnp1);
    cudaGetSymbolAddress((void**)&bnp2,    g_bnp2);

    // ---- Fork A: norm_all (s1) || knn0 (default) ----
    cudaEventRecord(g_ev[0], 0);
    cudaStreamWaitEvent(g_s1, g_ev[0], 0);
    norm_all_kernel<<<35, 256, 0, g_s1>>>(d0, dir1, dir2, dir3, dir4,
                                          d0n, dir1n, dir2n, dir3n, dir4n);
    cudaEventRecord(g_ev[1], g_s1);
    knn_warp_kernel<<<BATCH * NV / 8, 256>>>(x, NV, idx10_0, idx4_0, dirs0);
    cudaStreamWaitEvent(0, g_ev[1], 0);   // join before conv_surface (needs d0n)

    conv_surface_kernel<<<BATCH * NV, 32>>>(dirs0, d0n, fm0);
    gemm_tf32_kernel<<<dim3(1024 / 128, (BATCH * NV) / 128), 256>>>(fm0, w1, b1, feat1, BATCH * NV, 1024, 128);
    conv_layer_kernel<128><<<BATCH * NV, 32>>>(feat1, dirs0, idx10_0, dir1n, conv1, NV);
    bn_stats_kernel<<<dim3(128 / 32, 16), 256>>>(conv1, BATCH * NV, 128, bnp1, bnp2, mean, rstd);
    bn_apply_silu_kernel<<<(BATCH * NV * 128 + 255) / 256, 256>>>(conv1, mean, rstd, g1, bb1, fm1, BATCH * NV * 128, 128);
    pool_gather_kernel<128><<<BATCH * NP1, 32>>>(fm1, idx4_0, perm1, x, f1, v1, NV, NP1);

    // ---- Fork B: knn1 (s1) || gemm2 (default) ----
    cudaEventRecord(g_ev[2], 0);
    cudaStreamWaitEvent(g_s1, g_ev[2], 0);
    knn_warp_kernel<<<BATCH * NP1 / 8, 256, 0, g_s1>>>(v1, NP1, idx10_1, idx4_1, dirs1);
    cudaEventRecord(g_ev[3], g_s1);
    gemm_tf32_kernel<<<dim3(2048 / 128, (BATCH * NP1) / 128), 256>>>(f1, w2, b2, feat2, BATCH * NP1, 2048, 128);
    cudaStreamWaitEvent(0, g_ev[3], 0);   // join before conv2 (needs dirs1/idx10_1)

    conv_layer_kernel<256><<<BATCH * NP1, 64>>>(feat2, dirs1, idx10_1, dir2n, conv2, NP1);
    bn_stats_kernel<<<dim3(256 / 32, 16), 256>>>(conv2, BATCH * NP1, 256, bnp1, bnp2, mean, rstd);
    bn_apply_silu_kernel<<<(BATCH * NP1 * 256 + 255) / 256, 256>>>(conv2, mean, rstd, g2, bb2, fm2, BATCH * NP1 * 256, 256);
    gemm_tf32_kernel<<<dim3(2048 / 128, (BATCH * NP1) / 128), 256>>>(fm2, w3, b3, feat3, BATCH * NP1, 2048, 256);
    conv_layer_kernel<256><<<BATCH * NP1, 64>>>(feat3, dirs1, idx10_1, dir3n, conv3, NP1);
    bn_stats_kernel<<<dim3(256 / 32, 16), 256>>>(conv3, BATCH * NP1, 256, bnp1, bnp2, mean, rstd);
    bn_apply_silu_kernel<<<(BATCH * NP1 * 256 + 255) / 256, 256>>>(conv3, mean, rstd, g3, bb3, fm3, BATCH * NP1 * 256, 256);
    pool_gather_kernel<256><<<BATCH * NP2, 64>>>(fm3, idx4_1, perm2, v1, f2, v2, NP1, NP2);

    // ---- Fork C: knn2 (s1) + nearest (s2) || gemm4 (default) ----
    cudaEventRecord(g_ev[4], 0);
    cudaStreamWaitEvent(g_s1, g_ev[4], 0);
    cudaStreamWaitEvent(g_s2, g_ev[4], 0);
    knn_warp_kernel<<<BATCH * NP2 / 8, 256, 0, g_s1>>>(v2, NP2, idx10_2, (int*)0, dirs2);
    cudaEventRecord(g_ev[5], g_s1);
    nearest_both_kernel<<<BATCH * NV / 64, 64, 0, g_s2>>>(x, v1, v2, n1, n2);
    cudaEventRecord(g_ev[6], g_s2);
    gemm_tf32_kernel<<<dim3(4096 / 128, (BATCH * NP2) / 128), 256>>>(f2, w4, b4, feat4, BATCH * NP2, 4096, 256);
    cudaStreamWaitEvent(0, g_ev[5], 0);   // join knn2 before conv4
    conv_layer_kernel<512><<<BATCH * NP2, 128>>>(feat4, dirs2, idx10_2, dir4n, fm4, NP2);
    cudaStreamWaitEvent(0, g_ev[6], 0);   // join nearest before assemble
    assemble_kernel<<<BATCH * NV, 256>>>(fm0, fm1, fm2, fm3, fm4, n1, n2, out);
}